// round 1
// baseline (speedup 1.0000x reference)
#include <cuda_runtime.h>
#include <math.h>

#define NTOK 2048
#define DMOD 512
#define NH 8
#define HDIM 64
#define NBINS 16

// Scratch (no cudaMalloc allowed)
__device__ float g_Q[NTOK * DMOD];
__device__ float g_K[NTOK * DMOD];
__device__ float g_V[NTOK * DMOD];
__device__ float g_AO[NTOK * DMOD];

// ---------------------------------------------------------------------------
// Tiled SGEMM body: C[2048,512] = A[2048,512] @ W[512,512] + bias
// Block: 256 threads, 64x64 output tile, BK=16, 4x4 register micro-tile.
// Column assignment strided (tx + 16*j) -> conflict-free scalar smem reads.
// ---------------------------------------------------------------------------
__device__ __forceinline__ void gemm_body(const float* __restrict__ A,
                                          const float* __restrict__ W,
                                          const float* __restrict__ bias,
                                          float* __restrict__ C)
{
    __shared__ float As[16][65];   // A tile transposed: As[k][m]
    __shared__ float Bs[16][64];   // W tile: Bs[k][n]

    const int tid = threadIdx.x;
    const int tx = tid & 15;
    const int ty = tid >> 4;
    const int m0 = blockIdx.y * 64;
    const int n0 = blockIdx.x * 64;

    float acc[4][4] = {};

    for (int k0 = 0; k0 < DMOD; k0 += 16) {
        // Load A tile (64 rows x 16 k), transposed into As
        {
            int row = tid >> 2;
            int kq  = tid & 3;
            float4 a4 = *(const float4*)&A[(size_t)(m0 + row) * DMOD + k0 + kq * 4];
            As[kq * 4 + 0][row] = a4.x;
            As[kq * 4 + 1][row] = a4.y;
            As[kq * 4 + 2][row] = a4.z;
            As[kq * 4 + 3][row] = a4.w;
        }
        // Load W tile (16 k x 64 n)
        {
            int kr = tid >> 4;
            int cq = tid & 15;
            *(float4*)&Bs[kr][cq * 4] =
                *(const float4*)&W[(size_t)(k0 + kr) * DMOD + n0 + cq * 4];
        }
        __syncthreads();

        #pragma unroll
        for (int kk = 0; kk < 16; kk++) {
            float a[4], b[4];
            #pragma unroll
            for (int i = 0; i < 4; i++) a[i] = As[kk][ty * 4 + i];
            #pragma unroll
            for (int j = 0; j < 4; j++) b[j] = Bs[kk][tx + 16 * j];
            #pragma unroll
            for (int i = 0; i < 4; i++)
                #pragma unroll
                for (int j = 0; j < 4; j++)
                    acc[i][j] += a[i] * b[j];
        }
        __syncthreads();
    }

    #pragma unroll
    for (int i = 0; i < 4; i++) {
        int row = m0 + ty * 4 + i;
        #pragma unroll
        for (int j = 0; j < 4; j++) {
            int col = n0 + tx + 16 * j;
            C[(size_t)row * DMOD + col] = acc[i][j] + bias[col];
        }
    }
}

// Fused QKV projection: blockIdx.z selects which projection
__global__ __launch_bounds__(256) void qkv_kernel(
    const float* __restrict__ x,
    const float* __restrict__ Wq, const float* __restrict__ bq,
    const float* __restrict__ Wk, const float* __restrict__ bk,
    const float* __restrict__ Wv, const float* __restrict__ bv)
{
    const float* W;
    const float* b;
    float* C;
    if (blockIdx.z == 0)      { W = Wq; b = bq; C = g_Q; }
    else if (blockIdx.z == 1) { W = Wk; b = bk; C = g_K; }
    else                      { W = Wv; b = bv; C = g_V; }
    gemm_body(x, W, b, C);
}

__global__ __launch_bounds__(256) void outproj_kernel(
    const float* __restrict__ Wo, const float* __restrict__ bo,
    float* __restrict__ out)
{
    gemm_body(g_AO, Wo, bo, out);
}

// ---------------------------------------------------------------------------
// Fused flash-style attention with z-bin bias.
// Grid: (NTOK/64, NH). Block: 256 threads.
// Each block: one head, 64 query rows, streams keys in 64-row tiles.
// Online softmax in registers; bias tile preloaded into P buffer and used
// as the score-accumulator init.
// ---------------------------------------------------------------------------
__global__ __launch_bounds__(256) void attn_kernel(
    const float* __restrict__ zmat,
    const float* __restrict__ ztab)
{
    extern __shared__ float sm[];
    float* Qs = sm;                 // [64][65]
    float* Ks = Qs + 64 * 65;       // [64][65]
    float* Vs = Ks + 64 * 65;       // [64][65]
    float* Ps = Vs + 64 * 65;       // [64][65]  bias -> P
    __shared__ float zt[NBINS];

    const int h   = blockIdx.y;
    const int q0  = blockIdx.x * 64;
    const int tid = threadIdx.x;
    const int tx  = tid & 15;
    const int ty  = tid >> 4;

    if (tid < NBINS) zt[tid] = ztab[tid * NH + h];

    // Load Q tile, pre-scaled by 1/sqrt(HD)
    const float scale = 0.125f;
    for (int it = tid; it < 64 * 16; it += 256) {
        int r = it >> 4, dq = it & 15;
        float4 v = *(const float4*)&g_Q[(size_t)(q0 + r) * DMOD + h * HDIM + dq * 4];
        Qs[r * 65 + dq * 4 + 0] = v.x * scale;
        Qs[r * 65 + dq * 4 + 1] = v.y * scale;
        Qs[r * 65 + dq * 4 + 2] = v.z * scale;
        Qs[r * 65 + dq * 4 + 3] = v.w * scale;
    }

    float m_i[4], l_i[4], o[4][4];
    #pragma unroll
    for (int i = 0; i < 4; i++) {
        m_i[i] = -1e30f;
        l_i[i] = 0.0f;
        #pragma unroll
        for (int j = 0; j < 4; j++) o[i][j] = 0.0f;
    }

    for (int kt = 0; kt < NTOK / 64; kt++) {
        __syncthreads();  // protect Ks/Vs/Ps reuse (and Qs/zt on first iter)

        // Load K and V tiles
        for (int it = tid; it < 64 * 16; it += 256) {
            int r = it >> 4, dq = it & 15;
            float4 kv = *(const float4*)&g_K[(size_t)(kt * 64 + r) * DMOD + h * HDIM + dq * 4];
            Ks[r * 65 + dq * 4 + 0] = kv.x;
            Ks[r * 65 + dq * 4 + 1] = kv.y;
            Ks[r * 65 + dq * 4 + 2] = kv.z;
            Ks[r * 65 + dq * 4 + 3] = kv.w;
            float4 vv = *(const float4*)&g_V[(size_t)(kt * 64 + r) * DMOD + h * HDIM + dq * 4];
            Vs[r * 65 + dq * 4 + 0] = vv.x;
            Vs[r * 65 + dq * 4 + 1] = vv.y;
            Vs[r * 65 + dq * 4 + 2] = vv.z;
            Vs[r * 65 + dq * 4 + 3] = vv.w;
        }
        // Load z tile and convert to bias (matches ref: floor(z/5.0*16.0), clip)
        for (int it = tid; it < 64 * 64; it += 256) {
            int r = it >> 6, c = it & 63;
            float z = zmat[(size_t)(q0 + r) * NTOK + kt * 64 + c];
            int bin = (int)floorf(z / 5.0f * 16.0f);
            bin = max(0, min(NBINS - 1, bin));
            Ps[r * 65 + c] = zt[bin];
        }
        __syncthreads();

        // S = Q K^T * scale + bias   (bias is accumulator init)
        float s[4][4];
        #pragma unroll
        for (int i = 0; i < 4; i++)
            #pragma unroll
            for (int j = 0; j < 4; j++)
                s[i][j] = Ps[(ty * 4 + i) * 65 + tx + 16 * j];

        #pragma unroll 8
        for (int kk = 0; kk < 64; kk++) {
            float a[4], b[4];
            #pragma unroll
            for (int i = 0; i < 4; i++) a[i] = Qs[(ty * 4 + i) * 65 + kk];
            #pragma unroll
            for (int j = 0; j < 4; j++) b[j] = Ks[(tx + 16 * j) * 65 + kk];
            #pragma unroll
            for (int i = 0; i < 4; i++)
                #pragma unroll
                for (int j = 0; j < 4; j++)
                    s[i][j] += a[i] * b[j];
        }

        // Online softmax update; write P into Ps (each cell has 1 owner)
        #pragma unroll
        for (int i = 0; i < 4; i++) {
            float tm = s[i][0];
            #pragma unroll
            for (int j = 1; j < 4; j++) tm = fmaxf(tm, s[i][j]);
            #pragma unroll
            for (int d = 1; d < 16; d <<= 1)
                tm = fmaxf(tm, __shfl_xor_sync(0xffffffffu, tm, d));

            float m_new = fmaxf(m_i[i], tm);
            float cf = __expf(m_i[i] - m_new);
            m_i[i] = m_new;

            float ps = 0.0f;
            #pragma unroll
            for (int j = 0; j < 4; j++) {
                float p = __expf(s[i][j] - m_new);
                Ps[(ty * 4 + i) * 65 + tx + 16 * j] = p;
                ps += p;
            }
            #pragma unroll
            for (int d = 1; d < 16; d <<= 1)
                ps += __shfl_xor_sync(0xffffffffu, ps, d);

            l_i[i] = l_i[i] * cf + ps;
            #pragma unroll
            for (int j = 0; j < 4; j++) o[i][j] *= cf;
        }
        __syncthreads();

        // O += P @ V
        #pragma unroll 8
        for (int c = 0; c < 64; c++) {
            float p[4], v[4];
            #pragma unroll
            for (int i = 0; i < 4; i++) p[i] = Ps[(ty * 4 + i) * 65 + c];
            #pragma unroll
            for (int j = 0; j < 4; j++) v[j] = Vs[c * 65 + tx + 16 * j];
            #pragma unroll
            for (int i = 0; i < 4; i++)
                #pragma unroll
                for (int j = 0; j < 4; j++)
                    o[i][j] += p[i] * v[j];
        }
    }

    // Normalize and write attention output
    #pragma unroll
    for (int i = 0; i < 4; i++) {
        float inv = 1.0f / l_i[i];
        int row = q0 + ty * 4 + i;
        #pragma unroll
        for (int j = 0; j < 4; j++) {
            int d = tx + 16 * j;
            g_AO[(size_t)row * DMOD + h * HDIM + d] = o[i][j] * inv;
        }
    }
}

// ---------------------------------------------------------------------------

extern "C" void kernel_launch(void* const* d_in, const int* in_sizes, int n_in,
                              void* d_out, int out_size)
{
    const float* x  = (const float*)d_in[0];
    const float* z  = (const float*)d_in[1];
    const float* Wq = (const float*)d_in[2];
    const float* bq = (const float*)d_in[3];
    const float* Wk = (const float*)d_in[4];
    const float* bk = (const float*)d_in[5];
    const float* Wv = (const float*)d_in[6];
    const float* bv = (const float*)d_in[7];
    const float* Wo = (const float*)d_in[8];
    const float* bo = (const float*)d_in[9];
    const float* zt = (const float*)d_in[10];
    float* out = (float*)d_out;

    // Attention needs >48KB dynamic smem
    static const int ATTN_SMEM = 4 * 64 * 65 * (int)sizeof(float);
    cudaFuncSetAttribute(attn_kernel,
                         cudaFuncAttributeMaxDynamicSharedMemorySize, ATTN_SMEM);

    dim3 gemm_grid(DMOD / 64, NTOK / 64, 3);
    qkv_kernel<<<gemm_grid, 256>>>(x, Wq, bq, Wk, bk, Wv, bv);

    dim3 attn_grid(NTOK / 64, NH);
    attn_kernel<<<attn_grid, 256, ATTN_SMEM>>>(z, zt);

    dim3 out_grid(DMOD / 64, NTOK / 64, 1);
    outproj_kernel<<<out_grid, 256>>>(Wo, bo, out);
}

// round 3
// speedup vs baseline: 2.0382x; 2.0382x over previous
#include <cuda_runtime.h>
#include <cuda_bf16.h>
#include <math.h>
#include <stdint.h>

#define NTOK 2048
#define DMOD 512
#define NH 8
#define HDIM 64
#define NBINS 16

// ---------------------------------------------------------------------------
// Scratch (no cudaMalloc allowed)
// ---------------------------------------------------------------------------
__device__ float g_Q[NTOK * DMOD];
__device__ float g_K[NTOK * DMOD];
__device__ float g_V[NTOK * DMOD];
__device__ float g_AO[NTOK * DMOD];
__device__ __nv_bfloat16 g_Qh[NTOK * DMOD], g_Ql[NTOK * DMOD];   // [h][tok][64]
__device__ __nv_bfloat16 g_Kh[NTOK * DMOD], g_Kl[NTOK * DMOD];   // [h][tok][64]
__device__ __nv_bfloat16 g_Vth[NTOK * DMOD], g_Vtl[NTOK * DMOD]; // [h][d][2048]
__device__ uint8_t g_bins[NTOK * NTOK];

// ---------------------------------------------------------------------------
// mma.sync / cp.async helpers (sm_80-class; legal on plain sm_103 target)
// ---------------------------------------------------------------------------
__device__ __forceinline__ void mma_bf16(float* c, const uint32_t* a,
                                         uint32_t b0, uint32_t b1) {
    asm volatile(
        "mma.sync.aligned.m16n8k16.row.col.f32.bf16.bf16.f32 "
        "{%0,%1,%2,%3},{%4,%5,%6,%7},{%8,%9},{%0,%1,%2,%3};"
        : "+f"(c[0]), "+f"(c[1]), "+f"(c[2]), "+f"(c[3])
        : "r"(a[0]), "r"(a[1]), "r"(a[2]), "r"(a[3]), "r"(b0), "r"(b1));
}
__device__ __forceinline__ void cp16(uint32_t dst, const void* src) {
    asm volatile("cp.async.cg.shared.global [%0], [%1], 16;" :: "r"(dst), "l"(src));
}
__device__ __forceinline__ uint32_t smem_u32(const void* p) {
    uint32_t a;
    asm("{ .reg .u64 t; cvta.to.shared.u64 t, %1; cvt.u32.u64 %0, t; }"
        : "=r"(a) : "l"(p));
    return a;
}
__device__ __forceinline__ uint32_t pack2(float a, float b) {  // a -> lower half
    __nv_bfloat162 t;
    t.x = __float2bfloat16_rn(a);
    t.y = __float2bfloat16_rn(b);
    return *(uint32_t*)&t;
}

// smem stage layout (bytes). Pitches chosen so row stride ≡ 4 words (mod 32)
// -> B-fragment LDS.32 banks = 4*g + t : conflict-free. All 16B-aligned.
#define KP 144    // K pitch: 72 bf16
#define VP 272    // Vt pitch: 136 bf16
#define BP 144    // bins pitch
#define KH_O 0
#define KL_O 18432
#define VH_O 36864
#define VL_O 54272
#define BN_O 71680
#define STAGE 90112
#define ATTN_SMEM (2 * STAGE)

// ---------------------------------------------------------------------------
// Scalar SGEMM (validated R1): QKV + output projection
// ---------------------------------------------------------------------------
__device__ __forceinline__ void gemm_body(const float* __restrict__ A,
                                          const float* __restrict__ W,
                                          const float* __restrict__ bias,
                                          float* __restrict__ C)
{
    __shared__ float As[16][65];
    __shared__ float Bs[16][64];
    const int tid = threadIdx.x;
    const int tx = tid & 15;
    const int ty = tid >> 4;
    const int m0 = blockIdx.y * 64;
    const int n0 = blockIdx.x * 64;
    float acc[4][4] = {};

    for (int k0 = 0; k0 < DMOD; k0 += 16) {
        {
            int row = tid >> 2, kq = tid & 3;
            float4 a4 = *(const float4*)&A[(size_t)(m0 + row) * DMOD + k0 + kq * 4];
            As[kq * 4 + 0][row] = a4.x; As[kq * 4 + 1][row] = a4.y;
            As[kq * 4 + 2][row] = a4.z; As[kq * 4 + 3][row] = a4.w;
        }
        {
            int kr = tid >> 4, cq = tid & 15;
            *(float4*)&Bs[kr][cq * 4] = *(const float4*)&W[(size_t)(k0 + kr) * DMOD + n0 + cq * 4];
        }
        __syncthreads();
        #pragma unroll
        for (int kk = 0; kk < 16; kk++) {
            float a[4], b[4];
            #pragma unroll
            for (int i = 0; i < 4; i++) a[i] = As[kk][ty * 4 + i];
            #pragma unroll
            for (int j = 0; j < 4; j++) b[j] = Bs[kk][tx + 16 * j];
            #pragma unroll
            for (int i = 0; i < 4; i++)
                #pragma unroll
                for (int j = 0; j < 4; j++) acc[i][j] += a[i] * b[j];
        }
        __syncthreads();
    }
    #pragma unroll
    for (int i = 0; i < 4; i++) {
        int row = m0 + ty * 4 + i;
        #pragma unroll
        for (int j = 0; j < 4; j++) {
            int col = n0 + tx + 16 * j;
            C[(size_t)row * DMOD + col] = acc[i][j] + bias[col];
        }
    }
}

__global__ __launch_bounds__(256) void qkv_kernel(
    const float* __restrict__ x,
    const float* __restrict__ Wq, const float* __restrict__ bq,
    const float* __restrict__ Wk, const float* __restrict__ bk,
    const float* __restrict__ Wv, const float* __restrict__ bv)
{
    const float* W; const float* b; float* C;
    if (blockIdx.z == 0)      { W = Wq; b = bq; C = g_Q; }
    else if (blockIdx.z == 1) { W = Wk; b = bk; C = g_K; }
    else                      { W = Wv; b = bv; C = g_V; }
    gemm_body(x, W, b, C);
}

__global__ __launch_bounds__(256) void outproj_kernel(
    const float* __restrict__ Wo, const float* __restrict__ bo, float* __restrict__ out)
{
    gemm_body(g_AO, Wo, bo, out);
}

// ---------------------------------------------------------------------------
// Prep kernels: split fp32 -> bf16 hi/lo in attention-friendly layouts
// ---------------------------------------------------------------------------
__global__ __launch_bounds__(256) void prep_qk_kernel()
{
    int i = blockIdx.x * 256 + threadIdx.x;
    int tok = i >> 9, col = i & 511;
    int h = col >> 6, d = col & 63;
    size_t dst = ((size_t)h * NTOK + tok) * HDIM + d;

    float q = g_Q[i] * 0.125f;                   // fold 1/sqrt(64)
    __nv_bfloat16 qh = __float2bfloat16_rn(q);
    g_Qh[dst] = qh;
    g_Ql[dst] = __float2bfloat16_rn(q - __bfloat162float(qh));

    float k = g_K[i];
    __nv_bfloat16 kh = __float2bfloat16_rn(k);
    g_Kh[dst] = kh;
    g_Kl[dst] = __float2bfloat16_rn(k - __bfloat162float(kh));
}

__global__ void prep_v_kernel()
{
    __shared__ float ts[32][33];
    int tok0 = blockIdx.x * 32;
    int c0   = blockIdx.y * 32;
    int tx = threadIdx.x, ty = threadIdx.y;
    #pragma unroll
    for (int i = 0; i < 4; i++) {
        int r = ty + i * 8;
        ts[r][tx] = g_V[(size_t)(tok0 + r) * DMOD + c0 + tx];
    }
    __syncthreads();
    #pragma unroll
    for (int i = 0; i < 4; i++) {
        int dd = ty + i * 8;
        int col = c0 + dd, h = col >> 6, hd = col & 63;
        float v = ts[tx][dd];
        __nv_bfloat16 vh = __float2bfloat16_rn(v);
        size_t dst = ((size_t)h * HDIM + hd) * NTOK + tok0 + tx;
        g_Vth[dst] = vh;
        g_Vtl[dst] = __float2bfloat16_rn(v - __bfloat162float(vh));
    }
}

__device__ __forceinline__ uint8_t bin_of(float z) {
    int b = (int)floorf(z / 5.0f * 16.0f);
    return (uint8_t)max(0, min(NBINS - 1, b));
}
__global__ __launch_bounds__(256) void prep_bins_kernel(const float* __restrict__ zmat)
{
    size_t i = (size_t)blockIdx.x * 256 + threadIdx.x;
    float4 z = *(const float4*)(zmat + i * 4);
    uchar4 b;
    b.x = bin_of(z.x); b.y = bin_of(z.y); b.z = bin_of(z.z); b.w = bin_of(z.w);
    *(uchar4*)(g_bins + i * 4) = b;
}

// ---------------------------------------------------------------------------
// mma.sync flash attention. Grid (16 q-tiles, 8 heads), 256 threads (8 warps).
// Warp w owns q-rows [w*16, w*16+16). Per 128-key tile:
//   S(16x128) = Qh*Kh + Ql*Kh + Qh*Kl     (mma m16n8k16, fp32 accum)
//   P = exp(S + zt[bin]); split hi/lo; repack C-frags -> A-frags in regs
//   O(16x64) += Ph*Vh + Pl*Vh + Ph*Vl
// No max-subtraction (scores bounded); normalize by l at the end.
// Double-buffered cp.async for K/Vt/bins tiles.
// ---------------------------------------------------------------------------
__global__ __launch_bounds__(256, 1) void attn_mma_kernel(const float* __restrict__ ztab)
{
    extern __shared__ char smem[];
    __shared__ float zt[NBINS];

    const int tid = threadIdx.x;
    const int w   = tid >> 5;
    const int l   = tid & 31;
    const int g   = l >> 2;          // group (row within 8)
    const int t   = l & 3;           // thread-in-group (col pair)
    const int h   = blockIdx.y;
    const int q0  = blockIdx.x * 128;
    const int m0  = w * 16;

    if (tid < NBINS) zt[tid] = ztab[tid * NH + h];

    const uint32_t sbase = smem_u32(smem);

    // ---- async tile loader (K hi/lo, Vt hi/lo, bins) ----
    auto load_tile = [&](int kt, int stage) {
        uint32_t base = sbase + stage * STAGE;
        // K hi/lo: 128 rows x 128B
        #pragma unroll
        for (int p = 0; p < 4; p++) {
            int i = tid + p * 256;
            int r = i >> 3, c = i & 7;
            size_t go = (((size_t)h * NTOK + kt * 128 + r) * HDIM) * 2 + c * 16;
            uint32_t so = r * KP + c * 16;
            cp16(base + KH_O + so, (const char*)g_Kh + go);
            cp16(base + KL_O + so, (const char*)g_Kl + go);
        }
        // Vt hi/lo: 64 rows x 256B
        #pragma unroll
        for (int p = 0; p < 4; p++) {
            int i = tid + p * 256;
            int d = i >> 4, c = i & 15;
            size_t go = (((size_t)h * HDIM + d) * NTOK + kt * 128) * 2 + c * 16;
            uint32_t so = d * VP + c * 16;
            cp16(base + VH_O + so, (const char*)g_Vth + go);
            cp16(base + VL_O + so, (const char*)g_Vtl + go);
        }
        // bins: 128 rows x 128B
        #pragma unroll
        for (int p = 0; p < 4; p++) {
            int i = tid + p * 256;
            int r = i >> 3, c = i & 7;
            cp16(base + BN_O + r * BP + c * 16,
                 g_bins + (size_t)(q0 + r) * NTOK + kt * 128 + c * 16);
        }
        asm volatile("cp.async.commit_group;" ::: "memory");
    };

    load_tile(0, 0);

    // ---- Q fragments (persist across all key tiles): 4 k16-tiles, hi/lo ----
    uint32_t qh[4][4], ql[4][4];
    {
        const uint16_t* qb_h = (const uint16_t*)g_Qh + ((size_t)h * NTOK + q0 + m0) * HDIM;
        const uint16_t* qb_l = (const uint16_t*)g_Ql + ((size_t)h * NTOK + q0 + m0) * HDIM;
        #pragma unroll
        for (int kk = 0; kk < 4; kk++) {
            int c0 = 16 * kk + 2 * t;
            qh[kk][0] = *(const uint32_t*)(qb_h + (size_t)g * HDIM + c0);
            qh[kk][1] = *(const uint32_t*)(qb_h + (size_t)(g + 8) * HDIM + c0);
            qh[kk][2] = *(const uint32_t*)(qb_h + (size_t)g * HDIM + c0 + 8);
            qh[kk][3] = *(const uint32_t*)(qb_h + (size_t)(g + 8) * HDIM + c0 + 8);
            ql[kk][0] = *(const uint32_t*)(qb_l + (size_t)g * HDIM + c0);
            ql[kk][1] = *(const uint32_t*)(qb_l + (size_t)(g + 8) * HDIM + c0);
            ql[kk][2] = *(const uint32_t*)(qb_l + (size_t)g * HDIM + c0 + 8);
            ql[kk][3] = *(const uint32_t*)(qb_l + (size_t)(g + 8) * HDIM + c0 + 8);
        }
    }

    float oc[8][4];
    #pragma unroll
    for (int j = 0; j < 8; j++)
        #pragma unroll
        for (int i = 0; i < 4; i++) oc[j][i] = 0.0f;
    float l0 = 0.0f, l1 = 0.0f;

    for (int kt = 0; kt < NTOK / 128; kt++) {
        if (kt + 1 < NTOK / 128) {
            load_tile(kt + 1, (kt + 1) & 1);
            asm volatile("cp.async.wait_group 1;" ::: "memory");
        } else {
            asm volatile("cp.async.wait_group 0;" ::: "memory");
        }
        __syncthreads();

        const char* S = smem + (kt & 1) * STAGE;

        // ---- S = Qh*Kh + Ql*Kh + Qh*Kl  (16 n8-tiles, 4 k16-steps) ----
        float sc[16][4];
        #pragma unroll
        for (int j = 0; j < 16; j++)
            #pragma unroll
            for (int i = 0; i < 4; i++) sc[j][i] = 0.0f;

        #pragma unroll
        for (int kk = 0; kk < 4; kk++) {
            #pragma unroll
            for (int j = 0; j < 16; j++) {
                uint32_t off = (uint32_t)(8 * j + g) * KP + (uint32_t)(16 * kk + 2 * t) * 2;
                uint32_t kh0 = *(const uint32_t*)(S + KH_O + off);
                uint32_t kh1 = *(const uint32_t*)(S + KH_O + off + 16);
                uint32_t kl0 = *(const uint32_t*)(S + KL_O + off);
                uint32_t kl1 = *(const uint32_t*)(S + KL_O + off + 16);
                mma_bf16(sc[j], qh[kk], kh0, kh1);
                mma_bf16(sc[j], ql[kk], kh0, kh1);
                mma_bf16(sc[j], qh[kk], kl0, kl1);
            }
        }

        // ---- softmax epilogue: bias lookup, exp, split, repack C->A frags ----
        uint32_t ph[8][4], pl[8][4];
        const char* BN = S + BN_O;
        #pragma unroll
        for (int j = 0; j < 16; j++) {
            int col = 8 * j + 2 * t;
            uint16_t bA = *(const uint16_t*)(BN + (uint32_t)(m0 + g) * BP + col);
            uint16_t bB = *(const uint16_t*)(BN + (uint32_t)(m0 + g + 8) * BP + col);
            float p0 = __expf(sc[j][0] + zt[bA & 0xFF]);
            float p1 = __expf(sc[j][1] + zt[bA >> 8]);
            float p2 = __expf(sc[j][2] + zt[bB & 0xFF]);
            float p3 = __expf(sc[j][3] + zt[bB >> 8]);
            l0 += p0 + p1;
            l1 += p2 + p3;
            __nv_bfloat16 h0 = __float2bfloat16_rn(p0);
            __nv_bfloat16 h1 = __float2bfloat16_rn(p1);
            __nv_bfloat16 h2 = __float2bfloat16_rn(p2);
            __nv_bfloat16 h3 = __float2bfloat16_rn(p3);
            int kp = j >> 1, hf = (j & 1) * 2;
            __nv_bfloat162 u01; u01.x = h0; u01.y = h1;
            __nv_bfloat162 u23; u23.x = h2; u23.y = h3;
            ph[kp][hf + 0] = *(uint32_t*)&u01;
            ph[kp][hf + 1] = *(uint32_t*)&u23;
            pl[kp][hf + 0] = pack2(p0 - __bfloat162float(h0), p1 - __bfloat162float(h1));
            pl[kp][hf + 1] = pack2(p2 - __bfloat162float(h2), p3 - __bfloat162float(h3));
        }

        // ---- O += Ph*Vh + Pl*Vh + Ph*Vl  (8 n8-tiles over hdim, 8 k16-steps) ----
        #pragma unroll
        for (int kp = 0; kp < 8; kp++) {
            #pragma unroll
            for (int jj = 0; jj < 8; jj++) {
                uint32_t off = (uint32_t)(8 * jj + g) * VP + (uint32_t)(16 * kp + 2 * t) * 2;
                uint32_t vh0 = *(const uint32_t*)(S + VH_O + off);
                uint32_t vh1 = *(const uint32_t*)(S + VH_O + off + 16);
                uint32_t vl0 = *(const uint32_t*)(S + VL_O + off);
                uint32_t vl1 = *(const uint32_t*)(S + VL_O + off + 16);
                mma_bf16(oc[jj], ph[kp], vh0, vh1);
                mma_bf16(oc[jj], pl[kp], vh0, vh1);
                mma_bf16(oc[jj], ph[kp], vl0, vl1);
            }
        }
        __syncthreads();   // stage consumed; safe for next cp.async overwrite
    }

    // ---- finalize: reduce l across the quad, normalize, store ----
    l0 += __shfl_xor_sync(0xffffffffu, l0, 1);
    l0 += __shfl_xor_sync(0xffffffffu, l0, 2);
    l1 += __shfl_xor_sync(0xffffffffu, l1, 1);
    l1 += __shfl_xor_sync(0xffffffffu, l1, 2);
    float inv0 = 1.0f / l0, inv1 = 1.0f / l1;

    int r0 = q0 + m0 + g, r1 = r0 + 8;
    #pragma unroll
    for (int jj = 0; jj < 8; jj++) {
        int col = h * HDIM + 8 * jj + 2 * t;
        float2 v0 = make_float2(oc[jj][0] * inv0, oc[jj][1] * inv0);
        float2 v1 = make_float2(oc[jj][2] * inv1, oc[jj][3] * inv1);
        *(float2*)&g_AO[(size_t)r0 * DMOD + col] = v0;
        *(float2*)&g_AO[(size_t)r1 * DMOD + col] = v1;
    }
}

// ---------------------------------------------------------------------------

extern "C" void kernel_launch(void* const* d_in, const int* in_sizes, int n_in,
                              void* d_out, int out_size)
{
    const float* x  = (const float*)d_in[0];
    const float* z  = (const float*)d_in[1];
    const float* Wq = (const float*)d_in[2];
    const float* bq = (const float*)d_in[3];
    const float* Wk = (const float*)d_in[4];
    const float* bk = (const float*)d_in[5];
    const float* Wv = (const float*)d_in[6];
    const float* bv = (const float*)d_in[7];
    const float* Wo = (const float*)d_in[8];
    const float* bo = (const float*)d_in[9];
    const float* zt = (const float*)d_in[10];
    float* out = (float*)d_out;

    cudaFuncSetAttribute(attn_mma_kernel,
                         cudaFuncAttributeMaxDynamicSharedMemorySize, ATTN_SMEM);

    dim3 gemm_grid(DMOD / 64, NTOK / 64, 3);
    qkv_kernel<<<gemm_grid, 256>>>(x, Wq, bq, Wk, bk, Wv, bv);

    prep_bins_kernel<<<(NTOK * NTOK / 4) / 256, 256>>>(z);
    prep_qk_kernel<<<(NTOK * DMOD) / 256, 256>>>();
    prep_v_kernel<<<dim3(NTOK / 32, DMOD / 32), dim3(32, 8)>>>();

    attn_mma_kernel<<<dim3(NTOK / 128, NH), 256, ATTN_SMEM>>>(zt);

    dim3 out_grid(DMOD / 64, NTOK / 64, 1);
    outproj_kernel<<<out_grid, 256>>>(Wo, bo, out);
}

// round 5
// speedup vs baseline: 3.0463x; 1.4946x over previous
#include <cuda_runtime.h>
#include <cuda_bf16.h>
#include <math.h>
#include <stdint.h>

#define NTOK 2048
#define DMOD 512
#define NH 8
#define HDIM 64
#define NBINS 16

// ---------------------------------------------------------------------------
// Scratch (no cudaMalloc allowed). Only referenced from DEVICE code.
// ---------------------------------------------------------------------------
__device__ float g_QKV[NTOK * 1536];                             // QKV gemm out
__device__ __nv_bfloat16 g_Xh[NTOK * DMOD], g_Xl[NTOK * DMOD];   // split x
__device__ __nv_bfloat16 g_Wth[1536 * 512], g_Wtl[1536 * 512];   // (Wq|Wk|Wv)^T split
__device__ __nv_bfloat16 g_Woth[512 * 512], g_Wotl[512 * 512];   // Wo^T split
__device__ float g_bqkv[1536];
__device__ __nv_bfloat16 g_AOh[NTOK * DMOD], g_AOl[NTOK * DMOD]; // attn out split
__device__ __nv_bfloat16 g_Qh[NTOK * DMOD], g_Ql[NTOK * DMOD];   // [h][tok][64]
__device__ __nv_bfloat16 g_Kh[NTOK * DMOD], g_Kl[NTOK * DMOD];   // [h][tok][64]
__device__ __nv_bfloat16 g_Vth[NTOK * DMOD], g_Vtl[NTOK * DMOD]; // [h][d][2048]
__device__ uint8_t g_bins[NTOK * NTOK];

// ---------------------------------------------------------------------------
// mma.sync / cp.async helpers
// ---------------------------------------------------------------------------
__device__ __forceinline__ void mma_bf16(float* c, const uint32_t* a,
                                         uint32_t b0, uint32_t b1) {
    asm volatile(
        "mma.sync.aligned.m16n8k16.row.col.f32.bf16.bf16.f32 "
        "{%0,%1,%2,%3},{%4,%5,%6,%7},{%8,%9},{%0,%1,%2,%3};"
        : "+f"(c[0]), "+f"(c[1]), "+f"(c[2]), "+f"(c[3])
        : "r"(a[0]), "r"(a[1]), "r"(a[2]), "r"(a[3]), "r"(b0), "r"(b1));
}
__device__ __forceinline__ void cp16(uint32_t dst, const void* src) {
    asm volatile("cp.async.cg.shared.global [%0], [%1], 16;" :: "r"(dst), "l"(src));
}
__device__ __forceinline__ uint32_t smem_u32(const void* p) {
    uint32_t a;
    asm("{ .reg .u64 t; cvta.to.shared.u64 t, %1; cvt.u32.u64 %0, t; }"
        : "=r"(a) : "l"(p));
    return a;
}
__device__ __forceinline__ uint32_t pack2(float a, float b) {
    __nv_bfloat162 t;
    t.x = __float2bfloat16_rn(a);
    t.y = __float2bfloat16_rn(b);
    return *(uint32_t*)&t;
}

// ---------------------------------------------------------------------------
// Generic split-bf16 tensor-core GEMM:
//   C[M x N] = Ah/Al [M x 512] * (Bth/Btl [N x 512])^T + bias
// mode 0: QKV projection   (A=g_X*,  B=g_Wt*,  bias=g_bqkv, C=g_QKV,  ldc=1536)
// mode 1: out projection   (A=g_AO*, B=g_Wot*, bias=ext,    C=ext,    ldc=512)
// CTA: 128x128 tile, 256 threads (8 warps x 16 rows), k-chunk 32, double buf.
// Pitch 80B = 20 words: B-frag LDS banks (20g+t) all distinct -> conflict-free.
// ---------------------------------------------------------------------------
#define GPIT 80
#define GAH 0
#define GAL 10240
#define GBH 20480
#define GBL 30720
#define GSTAGE 40960
#define GEMM_SMEM (2 * GSTAGE)

__global__ __launch_bounds__(256, 2) void gemm_mma_kernel(
    int mode, const float* __restrict__ bias_ext, float* __restrict__ C_ext, int ldc)
{
    extern __shared__ char smem[];
    const __nv_bfloat16 *Ah, *Al, *Bth, *Btl;
    const float* bias;
    float* C;
    if (mode == 0) {
        Ah = g_Xh;  Al = g_Xl;  Bth = g_Wth;  Btl = g_Wtl;
        bias = g_bqkv; C = g_QKV;
    } else {
        Ah = g_AOh; Al = g_AOl; Bth = g_Woth; Btl = g_Wotl;
        bias = bias_ext; C = C_ext;
    }

    const int tid = threadIdx.x;
    const int w = tid >> 5, l = tid & 31, g = l >> 2, t = l & 3;
    const int n0 = blockIdx.x * 128;
    const int mb = blockIdx.y * 128;
    const uint32_t sbase = smem_u32(smem);

    auto load = [&](int kc, int st) {
        uint32_t b = sbase + st * GSTAGE;
        #pragma unroll
        for (int p = 0; p < 2; p++) {
            int i = tid + p * 256;
            int r = i >> 2, c = i & 3;
            uint32_t so = r * GPIT + c * 16;
            size_t ga = ((size_t)(mb + r) * 512 + kc * 32) * 2 + c * 16;
            cp16(b + GAH + so, (const char*)Ah + ga);
            cp16(b + GAL + so, (const char*)Al + ga);
            size_t gb = ((size_t)(n0 + r) * 512 + kc * 32) * 2 + c * 16;
            cp16(b + GBH + so, (const char*)Bth + gb);
            cp16(b + GBL + so, (const char*)Btl + gb);
        }
        asm volatile("cp.async.commit_group;" ::: "memory");
    };

    float acc[16][4];
    #pragma unroll
    for (int j = 0; j < 16; j++)
        #pragma unroll
        for (int i = 0; i < 4; i++) acc[j][i] = 0.0f;

    load(0, 0);
    for (int kc = 0; kc < 16; kc++) {
        if (kc + 1 < 16) {
            load(kc + 1, (kc + 1) & 1);
            asm volatile("cp.async.wait_group 1;" ::: "memory");
        } else {
            asm volatile("cp.async.wait_group 0;" ::: "memory");
        }
        __syncthreads();
        const char* S = smem + (kc & 1) * GSTAGE;

        #pragma unroll
        for (int kk = 0; kk < 2; kk++) {
            uint32_t ao = (uint32_t)(w * 16 + g) * GPIT + (uint32_t)(16 * kk + 2 * t) * 2;
            uint32_t ah[4], al[4];
            ah[0] = *(const uint32_t*)(S + GAH + ao);
            ah[1] = *(const uint32_t*)(S + GAH + ao + 8 * GPIT);
            ah[2] = *(const uint32_t*)(S + GAH + ao + 16);
            ah[3] = *(const uint32_t*)(S + GAH + ao + 8 * GPIT + 16);
            al[0] = *(const uint32_t*)(S + GAL + ao);
            al[1] = *(const uint32_t*)(S + GAL + ao + 8 * GPIT);
            al[2] = *(const uint32_t*)(S + GAL + ao + 16);
            al[3] = *(const uint32_t*)(S + GAL + ao + 8 * GPIT + 16);
            #pragma unroll
            for (int j = 0; j < 16; j++) {
                uint32_t bo = (uint32_t)(8 * j + g) * GPIT + (uint32_t)(16 * kk + 2 * t) * 2;
                uint32_t bh0 = *(const uint32_t*)(S + GBH + bo);
                uint32_t bh1 = *(const uint32_t*)(S + GBH + bo + 16);
                uint32_t bl0 = *(const uint32_t*)(S + GBL + bo);
                uint32_t bl1 = *(const uint32_t*)(S + GBL + bo + 16);
                mma_bf16(acc[j], ah, bh0, bh1);
                mma_bf16(acc[j], al, bh0, bh1);
                mma_bf16(acc[j], ah, bl0, bl1);
            }
        }
        __syncthreads();
    }

    const int r0 = mb + w * 16 + g, r1 = r0 + 8;
    #pragma unroll
    for (int j = 0; j < 16; j++) {
        int col = n0 + 8 * j + 2 * t;
        float b0 = bias[col], b1 = bias[col + 1];
        *(float2*)&C[(size_t)r0 * ldc + col] = make_float2(acc[j][0] + b0, acc[j][1] + b1);
        *(float2*)&C[(size_t)r1 * ldc + col] = make_float2(acc[j][2] + b0, acc[j][3] + b1);
    }
}

// ---------------------------------------------------------------------------
// Prep kernels (only harness pointers cross the launch boundary)
// ---------------------------------------------------------------------------
__global__ __launch_bounds__(256) void prep_x_kernel(const float* __restrict__ x)
{
    int i = blockIdx.x * 256 + threadIdx.x;
    float v = x[i];
    __nv_bfloat16 h = __float2bfloat16_rn(v);
    g_Xh[i] = h;
    g_Xl[i] = __float2bfloat16_rn(v - __bfloat162float(h));
}

__global__ void prep_w_kernel(const float* __restrict__ Wq, const float* __restrict__ Wk,
                              const float* __restrict__ Wv, const float* __restrict__ Wo)
{
    __shared__ float ts[32][33];
    const float* src;
    __nv_bfloat16 *dh, *dl;
    int nbase;
    if (blockIdx.z == 0)      { src = Wq; dh = g_Wth;  dl = g_Wtl;  nbase = 0; }
    else if (blockIdx.z == 1) { src = Wk; dh = g_Wth;  dl = g_Wtl;  nbase = 512; }
    else if (blockIdx.z == 2) { src = Wv; dh = g_Wth;  dl = g_Wtl;  nbase = 1024; }
    else                      { src = Wo; dh = g_Woth; dl = g_Wotl; nbase = 0; }

    int k0 = blockIdx.x * 32;
    int n0 = blockIdx.y * 32;
    int tx = threadIdx.x, ty = threadIdx.y;   // 32 x 8
    #pragma unroll
    for (int i = 0; i < 4; i++) {
        int r = ty + i * 8;
        ts[r][tx] = src[(size_t)(k0 + r) * 512 + n0 + tx];
    }
    __syncthreads();
    #pragma unroll
    for (int i = 0; i < 4; i++) {
        int nn = ty + i * 8;
        float v = ts[tx][nn];                 // element (k=k0+tx, n=n0+nn)
        __nv_bfloat16 h = __float2bfloat16_rn(v);
        size_t dst = (size_t)(nbase + n0 + nn) * 512 + k0 + tx;
        dh[dst] = h;
        dl[dst] = __float2bfloat16_rn(v - __bfloat162float(h));
    }
}

__global__ void prep_bias_kernel(const float* __restrict__ bq,
                                 const float* __restrict__ bk,
                                 const float* __restrict__ bv)
{
    int i = blockIdx.x * 256 + threadIdx.x;
    float v;
    if (i < 512) v = bq[i];
    else if (i < 1024) v = bk[i - 512];
    else v = bv[i - 1024];
    g_bqkv[i] = v;
}

__global__ __launch_bounds__(256) void prep_qk_kernel()
{
    int i = blockIdx.x * 256 + threadIdx.x;
    int tok = i >> 9, col = i & 511;
    int h = col >> 6, d = col & 63;
    size_t dst = ((size_t)h * NTOK + tok) * HDIM + d;

    float q = g_QKV[(size_t)tok * 1536 + col] * 0.125f;   // fold 1/sqrt(64)
    __nv_bfloat16 qh = __float2bfloat16_rn(q);
    g_Qh[dst] = qh;
    g_Ql[dst] = __float2bfloat16_rn(q - __bfloat162float(qh));

    float k = g_QKV[(size_t)tok * 1536 + 512 + col];
    __nv_bfloat16 kh = __float2bfloat16_rn(k);
    g_Kh[dst] = kh;
    g_Kl[dst] = __float2bfloat16_rn(k - __bfloat162float(kh));
}

__global__ void prep_v_kernel()
{
    __shared__ float ts[32][33];
    int tok0 = blockIdx.x * 32;
    int c0   = blockIdx.y * 32;
    int tx = threadIdx.x, ty = threadIdx.y;
    #pragma unroll
    for (int i = 0; i < 4; i++) {
        int r = ty + i * 8;
        ts[r][tx] = g_QKV[(size_t)(tok0 + r) * 1536 + 1024 + c0 + tx];
    }
    __syncthreads();
    #pragma unroll
    for (int i = 0; i < 4; i++) {
        int dd = ty + i * 8;
        int col = c0 + dd, h = col >> 6, hd = col & 63;
        float v = ts[tx][dd];
        __nv_bfloat16 vh = __float2bfloat16_rn(v);
        size_t dst = ((size_t)h * HDIM + hd) * NTOK + tok0 + tx;
        g_Vth[dst] = vh;
        g_Vtl[dst] = __float2bfloat16_rn(v - __bfloat162float(vh));
    }
}

__device__ __forceinline__ uint8_t bin_of(float z) {
    int b = (int)floorf(z / 5.0f * 16.0f);
    return (uint8_t)max(0, min(NBINS - 1, b));
}
__global__ __launch_bounds__(256) void prep_bins_kernel(const float* __restrict__ zmat)
{
    size_t i = (size_t)blockIdx.x * 256 + threadIdx.x;
    float4 z = *(const float4*)(zmat + i * 4);
    uchar4 b;
    b.x = bin_of(z.x); b.y = bin_of(z.y); b.z = bin_of(z.z); b.w = bin_of(z.w);
    *(uchar4*)(g_bins + i * 4) = b;
}

// ---------------------------------------------------------------------------
// mma.sync flash attention (validated R3). Writes split-bf16 AO directly.
// ---------------------------------------------------------------------------
#define KP 144
#define VP 272
#define BP 144
#define KH_O 0
#define KL_O 18432
#define VH_O 36864
#define VL_O 54272
#define BN_O 71680
#define STAGE 90112
#define ATTN_SMEM (2 * STAGE)

__global__ __launch_bounds__(256, 1) void attn_mma_kernel(const float* __restrict__ ztab)
{
    extern __shared__ char smem[];
    __shared__ float zt[NBINS];

    const int tid = threadIdx.x;
    const int w   = tid >> 5;
    const int l   = tid & 31;
    const int g   = l >> 2;
    const int t   = l & 3;
    const int h   = blockIdx.y;
    const int q0  = blockIdx.x * 128;
    const int m0  = w * 16;

    if (tid < NBINS) zt[tid] = ztab[tid * NH + h];

    const uint32_t sbase = smem_u32(smem);

    auto load_tile = [&](int kt, int stage) {
        uint32_t base = sbase + stage * STAGE;
        #pragma unroll
        for (int p = 0; p < 4; p++) {
            int i = tid + p * 256;
            int r = i >> 3, c = i & 7;
            size_t go = (((size_t)h * NTOK + kt * 128 + r) * HDIM) * 2 + c * 16;
            uint32_t so = r * KP + c * 16;
            cp16(base + KH_O + so, (const char*)g_Kh + go);
            cp16(base + KL_O + so, (const char*)g_Kl + go);
        }
        #pragma unroll
        for (int p = 0; p < 4; p++) {
            int i = tid + p * 256;
            int d = i >> 4, c = i & 15;
            size_t go = (((size_t)h * HDIM + d) * NTOK + kt * 128) * 2 + c * 16;
            uint32_t so = d * VP + c * 16;
            cp16(base + VH_O + so, (const char*)g_Vth + go);
            cp16(base + VL_O + so, (const char*)g_Vtl + go);
        }
        #pragma unroll
        for (int p = 0; p < 4; p++) {
            int i = tid + p * 256;
            int r = i >> 3, c = i & 7;
            cp16(base + BN_O + r * BP + c * 16,
                 g_bins + (size_t)(q0 + r) * NTOK + kt * 128 + c * 16);
        }
        asm volatile("cp.async.commit_group;" ::: "memory");
    };

    load_tile(0, 0);

    uint32_t qh[4][4], ql[4][4];
    {
        const uint16_t* qb_h = (const uint16_t*)g_Qh + ((size_t)h * NTOK + q0 + m0) * HDIM;
        const uint16_t* qb_l = (const uint16_t*)g_Ql + ((size_t)h * NTOK + q0 + m0) * HDIM;
        #pragma unroll
        for (int kk = 0; kk < 4; kk++) {
            int c0 = 16 * kk + 2 * t;
            qh[kk][0] = *(const uint32_t*)(qb_h + (size_t)g * HDIM + c0);
            qh[kk][1] = *(const uint32_t*)(qb_h + (size_t)(g + 8) * HDIM + c0);
            qh[kk][2] = *(const uint32_t*)(qb_h + (size_t)g * HDIM + c0 + 8);
            qh[kk][3] = *(const uint32_t*)(qb_h + (size_t)(g + 8) * HDIM + c0 + 8);
            ql[kk][0] = *(const uint32_t*)(qb_l + (size_t)g * HDIM + c0);
            ql[kk][1] = *(const uint32_t*)(qb_l + (size_t)(g + 8) * HDIM + c0);
            ql[kk][2] = *(const uint32_t*)(qb_l + (size_t)g * HDIM + c0 + 8);
            ql[kk][3] = *(const uint32_t*)(qb_l + (size_t)(g + 8) * HDIM + c0 + 8);
        }
    }

    float oc[8][4];
    #pragma unroll
    for (int j = 0; j < 8; j++)
        #pragma unroll
        for (int i = 0; i < 4; i++) oc[j][i] = 0.0f;
    float l0 = 0.0f, l1 = 0.0f;

    for (int kt = 0; kt < NTOK / 128; kt++) {
        if (kt + 1 < NTOK / 128) {
            load_tile(kt + 1, (kt + 1) & 1);
            asm volatile("cp.async.wait_group 1;" ::: "memory");
        } else {
            asm volatile("cp.async.wait_group 0;" ::: "memory");
        }
        __syncthreads();

        const char* S = smem + (kt & 1) * STAGE;

        float sc[16][4];
        #pragma unroll
        for (int j = 0; j < 16; j++)
            #pragma unroll
            for (int i = 0; i < 4; i++) sc[j][i] = 0.0f;

        #pragma unroll
        for (int kk = 0; kk < 4; kk++) {
            #pragma unroll
            for (int j = 0; j < 16; j++) {
                uint32_t off = (uint32_t)(8 * j + g) * KP + (uint32_t)(16 * kk + 2 * t) * 2;
                uint32_t kh0 = *(const uint32_t*)(S + KH_O + off);
                uint32_t kh1 = *(const uint32_t*)(S + KH_O + off + 16);
                uint32_t kl0 = *(const uint32_t*)(S + KL_O + off);
                uint32_t kl1 = *(const uint32_t*)(S + KL_O + off + 16);
                mma_bf16(sc[j], qh[kk], kh0, kh1);
                mma_bf16(sc[j], ql[kk], kh0, kh1);
                mma_bf16(sc[j], qh[kk], kl0, kl1);
            }
        }

        uint32_t ph[8][4], pl[8][4];
        const char* BN = S + BN_O;
        #pragma unroll
        for (int j = 0; j < 16; j++) {
            int col = 8 * j + 2 * t;
            uint16_t bA = *(const uint16_t*)(BN + (uint32_t)(m0 + g) * BP + col);
            uint16_t bB = *(const uint16_t*)(BN + (uint32_t)(m0 + g + 8) * BP + col);
            float p0 = __expf(sc[j][0] + zt[bA & 0xFF]);
            float p1 = __expf(sc[j][1] + zt[bA >> 8]);
            float p2 = __expf(sc[j][2] + zt[bB & 0xFF]);
            float p3 = __expf(sc[j][3] + zt[bB >> 8]);
            l0 += p0 + p1;
            l1 += p2 + p3;
            __nv_bfloat16 h0 = __float2bfloat16_rn(p0);
            __nv_bfloat16 h1 = __float2bfloat16_rn(p1);
            __nv_bfloat16 h2 = __float2bfloat16_rn(p2);
            __nv_bfloat16 h3 = __float2bfloat16_rn(p3);
            int kp = j >> 1, hf = (j & 1) * 2;
            __nv_bfloat162 u01; u01.x = h0; u01.y = h1;
            __nv_bfloat162 u23; u23.x = h2; u23.y = h3;
            ph[kp][hf + 0] = *(uint32_t*)&u01;
            ph[kp][hf + 1] = *(uint32_t*)&u23;
            pl[kp][hf + 0] = pack2(p0 - __bfloat162float(h0), p1 - __bfloat162float(h1));
            pl[kp][hf + 1] = pack2(p2 - __bfloat162float(h2), p3 - __bfloat162float(h3));
        }

        #pragma unroll
        for (int kp = 0; kp < 8; kp++) {
            #pragma unroll
            for (int jj = 0; jj < 8; jj++) {
                uint32_t off = (uint32_t)(8 * jj + g) * VP + (uint32_t)(16 * kp + 2 * t) * 2;
                uint32_t vh0 = *(const uint32_t*)(S + VH_O + off);
                uint32_t vh1 = *(const uint32_t*)(S + VH_O + off + 16);
                uint32_t vl0 = *(const uint32_t*)(S + VL_O + off);
                uint32_t vl1 = *(const uint32_t*)(S + VL_O + off + 16);
                mma_bf16(oc[jj], ph[kp], vh0, vh1);
                mma_bf16(oc[jj], pl[kp], vh0, vh1);
                mma_bf16(oc[jj], ph[kp], vl0, vl1);
            }
        }
        __syncthreads();
    }

    l0 += __shfl_xor_sync(0xffffffffu, l0, 1);
    l0 += __shfl_xor_sync(0xffffffffu, l0, 2);
    l1 += __shfl_xor_sync(0xffffffffu, l1, 1);
    l1 += __shfl_xor_sync(0xffffffffu, l1, 2);
    float inv0 = 1.0f / l0, inv1 = 1.0f / l1;

    int r0 = q0 + m0 + g, r1 = r0 + 8;
    #pragma unroll
    for (int jj = 0; jj < 8; jj++) {
        int col = h * HDIM + 8 * jj + 2 * t;
        float v00 = oc[jj][0] * inv0, v01 = oc[jj][1] * inv0;
        float v10 = oc[jj][2] * inv1, v11 = oc[jj][3] * inv1;
        __nv_bfloat16 h00 = __float2bfloat16_rn(v00);
        __nv_bfloat16 h01 = __float2bfloat16_rn(v01);
        __nv_bfloat16 h10 = __float2bfloat16_rn(v10);
        __nv_bfloat16 h11 = __float2bfloat16_rn(v11);
        __nv_bfloat162 u0; u0.x = h00; u0.y = h01;
        __nv_bfloat162 u1; u1.x = h10; u1.y = h11;
        *(uint32_t*)&g_AOh[(size_t)r0 * DMOD + col] = *(uint32_t*)&u0;
        *(uint32_t*)&g_AOh[(size_t)r1 * DMOD + col] = *(uint32_t*)&u1;
        *(uint32_t*)&g_AOl[(size_t)r0 * DMOD + col] =
            pack2(v00 - __bfloat162float(h00), v01 - __bfloat162float(h01));
        *(uint32_t*)&g_AOl[(size_t)r1 * DMOD + col] =
            pack2(v10 - __bfloat162float(h10), v11 - __bfloat162float(h11));
    }
}

// ---------------------------------------------------------------------------

extern "C" void kernel_launch(void* const* d_in, const int* in_sizes, int n_in,
                              void* d_out, int out_size)
{
    const float* x  = (const float*)d_in[0];
    const float* z  = (const float*)d_in[1];
    const float* Wq = (const float*)d_in[2];
    const float* bq = (const float*)d_in[3];
    const float* Wk = (const float*)d_in[4];
    const float* bk = (const float*)d_in[5];
    const float* Wv = (const float*)d_in[6];
    const float* bv = (const float*)d_in[7];
    const float* Wo = (const float*)d_in[8];
    const float* bo = (const float*)d_in[9];
    const float* zt = (const float*)d_in[10];
    float* out = (float*)d_out;

    cudaFuncSetAttribute(attn_mma_kernel,
                         cudaFuncAttributeMaxDynamicSharedMemorySize, ATTN_SMEM);
    cudaFuncSetAttribute(gemm_mma_kernel,
                         cudaFuncAttributeMaxDynamicSharedMemorySize, GEMM_SMEM);

    // input preps
    prep_bins_kernel<<<(NTOK * NTOK / 4) / 256, 256>>>(z);
    prep_x_kernel<<<(NTOK * DMOD) / 256, 256>>>(x);
    prep_w_kernel<<<dim3(16, 16, 4), dim3(32, 8)>>>(Wq, Wk, Wv, Wo);
    prep_bias_kernel<<<6, 256>>>(bq, bk, bv);

    // fused QKV projection (tensor cores), mode 0 binds device globals internally
    gemm_mma_kernel<<<dim3(12, 16), 256, GEMM_SMEM>>>(0, nullptr, nullptr, 1536);

    prep_qk_kernel<<<(NTOK * DMOD) / 256, 256>>>();
    prep_v_kernel<<<dim3(NTOK / 32, DMOD / 32), dim3(32, 8)>>>();

    attn_mma_kernel<<<dim3(NTOK / 128, NH), 256, ATTN_SMEM>>>(zt);

    // output projection (tensor cores), C = harness d_out, bias = harness bo
    gemm_mma_kernel<<<dim3(4, 16), 256, GEMM_SMEM>>>(1, bo, out, 512);
}

// round 6
// speedup vs baseline: 4.1820x; 1.3728x over previous
#include <cuda_runtime.h>
#include <cuda_bf16.h>
#include <cuda_fp16.h>
#include <math.h>
#include <stdint.h>

#define NTOK 2048
#define DMOD 512
#define NH 8
#define HDIM 64
#define NBINS 16

// ---------------------------------------------------------------------------
// Scratch (no cudaMalloc). Only referenced from DEVICE code.
// ---------------------------------------------------------------------------
__device__ float g_QKV[NTOK * 1536];                             // QKV gemm out
__device__ __nv_bfloat16 g_Xh[NTOK * DMOD], g_Xl[NTOK * DMOD];   // split x
__device__ __nv_bfloat16 g_Wth[1536 * 512], g_Wtl[1536 * 512];   // (Wq|Wk|Wv)^T split
__device__ __nv_bfloat16 g_Woth[512 * 512], g_Wotl[512 * 512];   // Wo^T split
__device__ __nv_bfloat16 g_AOh[NTOK * DMOD], g_AOl[NTOK * DMOD]; // attn out split
__device__ __half g_Qf[NTOK * DMOD];                             // [h][tok][64] fp16
__device__ __half g_Kf[NTOK * DMOD];                             // [h][tok][64] fp16
__device__ __half g_Vtf[NTOK * DMOD];                            // [h][d][2048] fp16
__device__ uint8_t g_bins[NTOK * NTOK];

#define LOG2E 1.4426950408889634f

// ---------------------------------------------------------------------------
// mma.sync / cp.async helpers
// ---------------------------------------------------------------------------
__device__ __forceinline__ void mma_bf16(float* c, const uint32_t* a,
                                         uint32_t b0, uint32_t b1) {
    asm volatile(
        "mma.sync.aligned.m16n8k16.row.col.f32.bf16.bf16.f32 "
        "{%0,%1,%2,%3},{%4,%5,%6,%7},{%8,%9},{%0,%1,%2,%3};"
        : "+f"(c[0]), "+f"(c[1]), "+f"(c[2]), "+f"(c[3])
        : "r"(a[0]), "r"(a[1]), "r"(a[2]), "r"(a[3]), "r"(b0), "r"(b1));
}
__device__ __forceinline__ void mma_fp16(float* c, const uint32_t* a,
                                         uint32_t b0, uint32_t b1) {
    asm volatile(
        "mma.sync.aligned.m16n8k16.row.col.f32.f16.f16.f32 "
        "{%0,%1,%2,%3},{%4,%5,%6,%7},{%8,%9},{%0,%1,%2,%3};"
        : "+f"(c[0]), "+f"(c[1]), "+f"(c[2]), "+f"(c[3])
        : "r"(a[0]), "r"(a[1]), "r"(a[2]), "r"(a[3]), "r"(b0), "r"(b1));
}
__device__ __forceinline__ void cp16(uint32_t dst, const void* src) {
    asm volatile("cp.async.cg.shared.global [%0], [%1], 16;" :: "r"(dst), "l"(src));
}
__device__ __forceinline__ uint32_t smem_u32(const void* p) {
    uint32_t a;
    asm("{ .reg .u64 t; cvta.to.shared.u64 t, %1; cvt.u32.u64 %0, t; }"
        : "=r"(a) : "l"(p));
    return a;
}
__device__ __forceinline__ uint32_t pack2bf(float a, float b) {
    __nv_bfloat162 t;
    t.x = __float2bfloat16_rn(a);
    t.y = __float2bfloat16_rn(b);
    return *(uint32_t*)&t;
}
__device__ __forceinline__ uint32_t pack2h(float a, float b) {
    __half2 t;
    t.x = __float2half_rn(a);
    t.y = __float2half_rn(b);
    return *(uint32_t*)&t;
}
__device__ __forceinline__ float fast_exp2(float x) {
    float r;
    asm("ex2.approx.ftz.f32 %0, %1;" : "=f"(r) : "f"(x));
    return r;
}

// ---------------------------------------------------------------------------
// Split-bf16 tensor-core GEMM (validated R5):
//   C[M x N] = Ah/Al [M x 512] * (Bth/Btl [N x 512])^T + bias
// mode 0: QKV (A=g_X*, B=g_Wt*, bias = bq|bk|bv concat in epilogue, C=g_QKV)
// mode 1: out projection (A=g_AO*, B=g_Wot*, bias=b0, C=C_ext)
// ---------------------------------------------------------------------------
#define GPIT 80
#define GAH 0
#define GAL 10240
#define GBH 20480
#define GBL 30720
#define GSTAGE 40960
#define GEMM_SMEM (2 * GSTAGE)

__global__ __launch_bounds__(256, 2) void gemm_mma_kernel(
    int mode, const float* __restrict__ b0p, const float* __restrict__ b1p,
    const float* __restrict__ b2p, float* __restrict__ C_ext, int ldc)
{
    extern __shared__ char smem[];
    const __nv_bfloat16 *Ah, *Al, *Bth, *Btl;
    float* C;
    if (mode == 0) {
        Ah = g_Xh;  Al = g_Xl;  Bth = g_Wth;  Btl = g_Wtl;  C = g_QKV;
    } else {
        Ah = g_AOh; Al = g_AOl; Bth = g_Woth; Btl = g_Wotl; C = C_ext;
    }

    const int tid = threadIdx.x;
    const int w = tid >> 5, l = tid & 31, g = l >> 2, t = l & 3;
    const int n0 = blockIdx.x * 128;
    const int mb = blockIdx.y * 128;
    const uint32_t sbase = smem_u32(smem);

    auto load = [&](int kc, int st) {
        uint32_t b = sbase + st * GSTAGE;
        #pragma unroll
        for (int p = 0; p < 2; p++) {
            int i = tid + p * 256;
            int r = i >> 2, c = i & 3;
            uint32_t so = r * GPIT + c * 16;
            size_t ga = ((size_t)(mb + r) * 512 + kc * 32) * 2 + c * 16;
            cp16(b + GAH + so, (const char*)Ah + ga);
            cp16(b + GAL + so, (const char*)Al + ga);
            size_t gb = ((size_t)(n0 + r) * 512 + kc * 32) * 2 + c * 16;
            cp16(b + GBH + so, (const char*)Bth + gb);
            cp16(b + GBL + so, (const char*)Btl + gb);
        }
        asm volatile("cp.async.commit_group;" ::: "memory");
    };

    float acc[16][4];
    #pragma unroll
    for (int j = 0; j < 16; j++)
        #pragma unroll
        for (int i = 0; i < 4; i++) acc[j][i] = 0.0f;

    load(0, 0);
    for (int kc = 0; kc < 16; kc++) {
        if (kc + 1 < 16) {
            load(kc + 1, (kc + 1) & 1);
            asm volatile("cp.async.wait_group 1;" ::: "memory");
        } else {
            asm volatile("cp.async.wait_group 0;" ::: "memory");
        }
        __syncthreads();
        const char* S = smem + (kc & 1) * GSTAGE;

        #pragma unroll
        for (int kk = 0; kk < 2; kk++) {
            uint32_t ao = (uint32_t)(w * 16 + g) * GPIT + (uint32_t)(16 * kk + 2 * t) * 2;
            uint32_t ah[4], al[4];
            ah[0] = *(const uint32_t*)(S + GAH + ao);
            ah[1] = *(const uint32_t*)(S + GAH + ao + 8 * GPIT);
            ah[2] = *(const uint32_t*)(S + GAH + ao + 16);
            ah[3] = *(const uint32_t*)(S + GAH + ao + 8 * GPIT + 16);
            al[0] = *(const uint32_t*)(S + GAL + ao);
            al[1] = *(const uint32_t*)(S + GAL + ao + 8 * GPIT);
            al[2] = *(const uint32_t*)(S + GAL + ao + 16);
            al[3] = *(const uint32_t*)(S + GAL + ao + 8 * GPIT + 16);
            #pragma unroll
            for (int j = 0; j < 16; j++) {
                uint32_t bo = (uint32_t)(8 * j + g) * GPIT + (uint32_t)(16 * kk + 2 * t) * 2;
                uint32_t bh0 = *(const uint32_t*)(S + GBH + bo);
                uint32_t bh1 = *(const uint32_t*)(S + GBH + bo + 16);
                uint32_t bl0 = *(const uint32_t*)(S + GBL + bo);
                uint32_t bl1 = *(const uint32_t*)(S + GBL + bo + 16);
                mma_bf16(acc[j], ah, bh0, bh1);
                mma_bf16(acc[j], al, bh0, bh1);
                mma_bf16(acc[j], ah, bl0, bl1);
            }
        }
        __syncthreads();
    }

    const int r0 = mb + w * 16 + g, r1 = r0 + 8;
    #pragma unroll
    for (int j = 0; j < 16; j++) {
        int col = n0 + 8 * j + 2 * t;
        float bv0, bv1;
        if (mode == 0) {
            const float* bp = (col < 512) ? b0p : (col < 1024 ? b1p : b2p);
            int cc = col & 511;
            bv0 = bp[cc];
            bv1 = bp[cc + 1];
        } else {
            bv0 = b0p[col];
            bv1 = b0p[col + 1];
        }
        *(float2*)&C[(size_t)r0 * ldc + col] = make_float2(acc[j][0] + bv0, acc[j][1] + bv1);
        *(float2*)&C[(size_t)r1 * ldc + col] = make_float2(acc[j][2] + bv0, acc[j][3] + bv1);
    }
}

// ---------------------------------------------------------------------------
// Fused input prep: blocks [0,1024) transpose+split W; blocks [1024,5120) split x
// ---------------------------------------------------------------------------
__global__ __launch_bounds__(256) void prep_in_kernel(
    const float* __restrict__ x,
    const float* __restrict__ Wq, const float* __restrict__ Wk,
    const float* __restrict__ Wv, const float* __restrict__ Wo)
{
    int bx = blockIdx.x;
    int tid = threadIdx.x;
    if (bx < 1024) {
        __shared__ float ts[32][33];
        int zb = bx >> 8, rem = bx & 255;
        int k0 = (rem & 15) * 32;
        int n0 = (rem >> 4) * 32;
        const float* src;
        __nv_bfloat16 *dh, *dl;
        int nbase;
        if (zb == 0)      { src = Wq; dh = g_Wth;  dl = g_Wtl;  nbase = 0; }
        else if (zb == 1) { src = Wk; dh = g_Wth;  dl = g_Wtl;  nbase = 512; }
        else if (zb == 2) { src = Wv; dh = g_Wth;  dl = g_Wtl;  nbase = 1024; }
        else              { src = Wo; dh = g_Woth; dl = g_Wotl; nbase = 0; }
        int tx = tid & 31, ty = tid >> 5;
        #pragma unroll
        for (int i = 0; i < 4; i++) {
            int r = ty + i * 8;
            ts[r][tx] = src[(size_t)(k0 + r) * 512 + n0 + tx];
        }
        __syncthreads();
        #pragma unroll
        for (int i = 0; i < 4; i++) {
            int nn = ty + i * 8;
            float v = ts[tx][nn];
            __nv_bfloat16 h = __float2bfloat16_rn(v);
            size_t dst = (size_t)(nbase + n0 + nn) * 512 + k0 + tx;
            dh[dst] = h;
            dl[dst] = __float2bfloat16_rn(v - __bfloat162float(h));
        }
    } else {
        int i = (bx - 1024) * 256 + tid;
        float v = x[i];
        __nv_bfloat16 h = __float2bfloat16_rn(v);
        g_Xh[i] = h;
        g_Xl[i] = __float2bfloat16_rn(v - __bfloat162float(h));
    }
}

// ---------------------------------------------------------------------------
// Fused QKV post-prep: blocks [0,1024) transpose V -> fp16; [1024,5120) Q/K fp16
// ---------------------------------------------------------------------------
__global__ __launch_bounds__(256) void prep_qkv_kernel()
{
    int bx = blockIdx.x;
    int tid = threadIdx.x;
    if (bx < 1024) {
        __shared__ float ts[32][33];
        int tok0 = (bx & 63) * 32;
        int c0   = (bx >> 6) * 32;
        int tx = tid & 31, ty = tid >> 5;
        #pragma unroll
        for (int i = 0; i < 4; i++) {
            int r = ty + i * 8;
            ts[r][tx] = g_QKV[(size_t)(tok0 + r) * 1536 + 1024 + c0 + tx];
        }
        __syncthreads();
        #pragma unroll
        for (int i = 0; i < 4; i++) {
            int dd = ty + i * 8;
            int col = c0 + dd, h = col >> 6, hd = col & 63;
            g_Vtf[((size_t)h * HDIM + hd) * NTOK + tok0 + tx] = __float2half_rn(ts[tx][dd]);
        }
    } else {
        int i = (bx - 1024) * 256 + tid;
        int tok = i >> 9, col = i & 511;
        int h = col >> 6, d = col & 63;
        size_t dst = ((size_t)h * NTOK + tok) * HDIM + d;
        // fold 1/sqrt(64) * log2(e) into Q for base-2 softmax
        g_Qf[dst] = __float2half_rn(g_QKV[(size_t)tok * 1536 + col] * (0.125f * LOG2E));
        g_Kf[dst] = __float2half_rn(g_QKV[(size_t)tok * 1536 + 512 + col]);
    }
}

__device__ __forceinline__ uint8_t bin_of(float z) {
    int b = (int)floorf(z / 5.0f * 16.0f);
    return (uint8_t)max(0, min(NBINS - 1, b));
}
__global__ __launch_bounds__(256) void prep_bins_kernel(const float* __restrict__ zmat)
{
    size_t i = (size_t)blockIdx.x * 256 + threadIdx.x;
    float4 z = *(const float4*)(zmat + i * 4);
    uchar4 b;
    b.x = bin_of(z.x); b.y = bin_of(z.y); b.z = bin_of(z.z); b.w = bin_of(z.w);
    *(uchar4*)(g_bins + i * 4) = b;
}

// ---------------------------------------------------------------------------
// fp16 single-term mma.sync flash attention.
// S (16x128 per warp) = Q*K^T (1 MMA per tile); P = 2^(S + zt2[bin]);
// O (16x64) += P*V (1 MMA per tile). fp32 accum everywhere, no max-sub.
// Writes split-bf16 AO for the 3-term outproj GEMM.
// ---------------------------------------------------------------------------
#define KP 144
#define VP 272
#define BP 144
#define KF_O 0
#define VT_O 18432
#define BN_O 35840
#define STAGE 54272
#define ATTN_SMEM (2 * STAGE)

__global__ __launch_bounds__(256, 1) void attn_mma_kernel(const float* __restrict__ ztab)
{
    extern __shared__ char smem[];
    __shared__ float zt[NBINS];

    const int tid = threadIdx.x;
    const int w   = tid >> 5;
    const int l   = tid & 31;
    const int g   = l >> 2;
    const int t   = l & 3;
    const int h   = blockIdx.y;
    const int q0  = blockIdx.x * 128;
    const int m0  = w * 16;

    if (tid < NBINS) zt[tid] = ztab[tid * NH + h] * LOG2E;   // base-2 bias

    const uint32_t sbase = smem_u32(smem);

    auto load_tile = [&](int kt, int stage) {
        uint32_t base = sbase + stage * STAGE;
        #pragma unroll
        for (int p = 0; p < 4; p++) {
            int i = tid + p * 256;
            int r = i >> 3, c = i & 7;
            cp16(base + KF_O + r * KP + c * 16,
                 (const char*)g_Kf + (((size_t)h * NTOK + kt * 128 + r) * HDIM) * 2 + c * 16);
        }
        #pragma unroll
        for (int p = 0; p < 4; p++) {
            int i = tid + p * 256;
            int d = i >> 4, c = i & 15;
            cp16(base + VT_O + d * VP + c * 16,
                 (const char*)g_Vtf + (((size_t)h * HDIM + d) * NTOK + kt * 128) * 2 + c * 16);
        }
        #pragma unroll
        for (int p = 0; p < 4; p++) {
            int i = tid + p * 256;
            int r = i >> 3, c = i & 7;
            cp16(base + BN_O + r * BP + c * 16,
                 g_bins + (size_t)(q0 + r) * NTOK + kt * 128 + c * 16);
        }
        asm volatile("cp.async.commit_group;" ::: "memory");
    };

    load_tile(0, 0);

    // Q fragments (persist): 4 k16-tiles
    uint32_t qf[4][4];
    {
        const uint16_t* qb = (const uint16_t*)g_Qf + ((size_t)h * NTOK + q0 + m0) * HDIM;
        #pragma unroll
        for (int kk = 0; kk < 4; kk++) {
            int c0 = 16 * kk + 2 * t;
            qf[kk][0] = *(const uint32_t*)(qb + (size_t)g * HDIM + c0);
            qf[kk][1] = *(const uint32_t*)(qb + (size_t)(g + 8) * HDIM + c0);
            qf[kk][2] = *(const uint32_t*)(qb + (size_t)g * HDIM + c0 + 8);
            qf[kk][3] = *(const uint32_t*)(qb + (size_t)(g + 8) * HDIM + c0 + 8);
        }
    }

    float oc[8][4];
    #pragma unroll
    for (int j = 0; j < 8; j++)
        #pragma unroll
        for (int i = 0; i < 4; i++) oc[j][i] = 0.0f;
    float l0 = 0.0f, l1 = 0.0f;

    for (int kt = 0; kt < NTOK / 128; kt++) {
        if (kt + 1 < NTOK / 128) {
            load_tile(kt + 1, (kt + 1) & 1);
            asm volatile("cp.async.wait_group 1;" ::: "memory");
        } else {
            asm volatile("cp.async.wait_group 0;" ::: "memory");
        }
        __syncthreads();

        const char* S = smem + (kt & 1) * STAGE;

        // S = Q K^T (base-2 scaled)
        float sc[16][4];
        #pragma unroll
        for (int j = 0; j < 16; j++)
            #pragma unroll
            for (int i = 0; i < 4; i++) sc[j][i] = 0.0f;

        #pragma unroll
        for (int kk = 0; kk < 4; kk++) {
            #pragma unroll
            for (int j = 0; j < 16; j++) {
                uint32_t off = (uint32_t)(8 * j + g) * KP + (uint32_t)(16 * kk + 2 * t) * 2;
                uint32_t k0 = *(const uint32_t*)(S + KF_O + off);
                uint32_t k1 = *(const uint32_t*)(S + KF_O + off + 16);
                mma_fp16(sc[j], qf[kk], k0, k1);
            }
        }

        // softmax epilogue: p = 2^(s + bias2); pack fp16 A-fragments
        uint32_t ph[8][4];
        const char* BN = S + BN_O;
        #pragma unroll
        for (int j = 0; j < 16; j++) {
            int col = 8 * j + 2 * t;
            uint16_t bA = *(const uint16_t*)(BN + (uint32_t)(m0 + g) * BP + col);
            uint16_t bB = *(const uint16_t*)(BN + (uint32_t)(m0 + g + 8) * BP + col);
            float p0 = fast_exp2(sc[j][0] + zt[bA & 0xFF]);
            float p1 = fast_exp2(sc[j][1] + zt[bA >> 8]);
            float p2 = fast_exp2(sc[j][2] + zt[bB & 0xFF]);
            float p3 = fast_exp2(sc[j][3] + zt[bB >> 8]);
            l0 += p0 + p1;
            l1 += p2 + p3;
            int kp = j >> 1, hf = (j & 1) * 2;
            ph[kp][hf + 0] = pack2h(p0, p1);
            ph[kp][hf + 1] = pack2h(p2, p3);
        }

        // O += P V
        #pragma unroll
        for (int kp = 0; kp < 8; kp++) {
            #pragma unroll
            for (int jj = 0; jj < 8; jj++) {
                uint32_t off = (uint32_t)(8 * jj + g) * VP + (uint32_t)(16 * kp + 2 * t) * 2;
                uint32_t v0 = *(const uint32_t*)(S + VT_O + off);
                uint32_t v1 = *(const uint32_t*)(S + VT_O + off + 16);
                mma_fp16(oc[jj], ph[kp], v0, v1);
            }
        }
        __syncthreads();
    }

    l0 += __shfl_xor_sync(0xffffffffu, l0, 1);
    l0 += __shfl_xor_sync(0xffffffffu, l0, 2);
    l1 += __shfl_xor_sync(0xffffffffu, l1, 1);
    l1 += __shfl_xor_sync(0xffffffffu, l1, 2);
    float inv0 = 1.0f / l0, inv1 = 1.0f / l1;

    int r0 = q0 + m0 + g, r1 = r0 + 8;
    #pragma unroll
    for (int jj = 0; jj < 8; jj++) {
        int col = h * HDIM + 8 * jj + 2 * t;
        float v00 = oc[jj][0] * inv0, v01 = oc[jj][1] * inv0;
        float v10 = oc[jj][2] * inv1, v11 = oc[jj][3] * inv1;
        __nv_bfloat16 h00 = __float2bfloat16_rn(v00);
        __nv_bfloat16 h01 = __float2bfloat16_rn(v01);
        __nv_bfloat16 h10 = __float2bfloat16_rn(v10);
        __nv_bfloat16 h11 = __float2bfloat16_rn(v11);
        __nv_bfloat162 u0; u0.x = h00; u0.y = h01;
        __nv_bfloat162 u1; u1.x = h10; u1.y = h11;
        *(uint32_t*)&g_AOh[(size_t)r0 * DMOD + col] = *(uint32_t*)&u0;
        *(uint32_t*)&g_AOh[(size_t)r1 * DMOD + col] = *(uint32_t*)&u1;
        *(uint32_t*)&g_AOl[(size_t)r0 * DMOD + col] =
            pack2bf(v00 - __bfloat162float(h00), v01 - __bfloat162float(h01));
        *(uint32_t*)&g_AOl[(size_t)r1 * DMOD + col] =
            pack2bf(v10 - __bfloat162float(h10), v11 - __bfloat162float(h11));
    }
}

// ---------------------------------------------------------------------------

extern "C" void kernel_launch(void* const* d_in, const int* in_sizes, int n_in,
                              void* d_out, int out_size)
{
    const float* x  = (const float*)d_in[0];
    const float* z  = (const float*)d_in[1];
    const float* Wq = (const float*)d_in[2];
    const float* bq = (const float*)d_in[3];
    const float* Wk = (const float*)d_in[4];
    const float* bk = (const float*)d_in[5];
    const float* Wv = (const float*)d_in[6];
    const float* bv = (const float*)d_in[7];
    const float* Wo = (const float*)d_in[8];
    const float* bo = (const float*)d_in[9];
    const float* zt = (const float*)d_in[10];
    float* out = (float*)d_out;

    cudaFuncSetAttribute(attn_mma_kernel,
                         cudaFuncAttributeMaxDynamicSharedMemorySize, ATTN_SMEM);
    cudaFuncSetAttribute(gemm_mma_kernel,
                         cudaFuncAttributeMaxDynamicSharedMemorySize, GEMM_SMEM);

    prep_bins_kernel<<<(NTOK * NTOK / 4) / 256, 256>>>(z);
    prep_in_kernel<<<1024 + (NTOK * DMOD) / 256, 256>>>(x, Wq, Wk, Wv, Wo);

    // fused QKV projection; bias concat handled in epilogue
    gemm_mma_kernel<<<dim3(12, 16), 256, GEMM_SMEM>>>(0, bq, bk, bv, nullptr, 1536);

    prep_qkv_kernel<<<1024 + (NTOK * DMOD) / 256, 256>>>();

    attn_mma_kernel<<<dim3(NTOK / 128, NH), 256, ATTN_SMEM>>>(zt);

    // output projection
    gemm_mma_kernel<<<dim3(4, 16), 256, GEMM_SMEM>>>(1, bo, nullptr, nullptr, out, 512);
}

// round 7
// speedup vs baseline: 4.2575x; 1.0181x over previous
#include <cuda_runtime.h>
#include <cuda_bf16.h>
#include <cuda_fp16.h>
#include <math.h>
#include <stdint.h>

#define NTOK 2048
#define DMOD 512
#define NH 8
#define HDIM 64
#define NBINS 16

// ---------------------------------------------------------------------------
// Scratch (no cudaMalloc). Only referenced from DEVICE code.
// ---------------------------------------------------------------------------
__device__ float g_Vc[NTOK * DMOD];                              // V proj (fp32, compact)
__device__ __nv_bfloat16 g_Xh[NTOK * DMOD], g_Xl[NTOK * DMOD];   // split x
__device__ __nv_bfloat16 g_Wth[1536 * 512], g_Wtl[1536 * 512];   // (Wq|Wk|Wv)^T split
__device__ __nv_bfloat16 g_Woth[512 * 512], g_Wotl[512 * 512];   // Wo^T split
__device__ __nv_bfloat16 g_AOh[NTOK * DMOD], g_AOl[NTOK * DMOD]; // attn out split
__device__ __half g_Qf[NTOK * DMOD];                             // [h][tok][64] fp16
__device__ __half g_Kf[NTOK * DMOD];                             // [h][tok][64] fp16
__device__ __half g_Vtf[NTOK * DMOD];                            // [h][d][2048] fp16
__device__ uint8_t g_bins[NTOK * NTOK];

#define LOG2E 1.4426950408889634f

// ---------------------------------------------------------------------------
// mma.sync / cp.async helpers
// ---------------------------------------------------------------------------
__device__ __forceinline__ void mma_bf16(float* c, const uint32_t* a,
                                         uint32_t b0, uint32_t b1) {
    asm volatile(
        "mma.sync.aligned.m16n8k16.row.col.f32.bf16.bf16.f32 "
        "{%0,%1,%2,%3},{%4,%5,%6,%7},{%8,%9},{%0,%1,%2,%3};"
        : "+f"(c[0]), "+f"(c[1]), "+f"(c[2]), "+f"(c[3])
        : "r"(a[0]), "r"(a[1]), "r"(a[2]), "r"(a[3]), "r"(b0), "r"(b1));
}
__device__ __forceinline__ void mma_fp16(float* c, const uint32_t* a,
                                         uint32_t b0, uint32_t b1) {
    asm volatile(
        "mma.sync.aligned.m16n8k16.row.col.f32.f16.f16.f32 "
        "{%0,%1,%2,%3},{%4,%5,%6,%7},{%8,%9},{%0,%1,%2,%3};"
        : "+f"(c[0]), "+f"(c[1]), "+f"(c[2]), "+f"(c[3])
        : "r"(a[0]), "r"(a[1]), "r"(a[2]), "r"(a[3]), "r"(b0), "r"(b1));
}
__device__ __forceinline__ void cp16(uint32_t dst, const void* src) {
    asm volatile("cp.async.cg.shared.global [%0], [%1], 16;" :: "r"(dst), "l"(src));
}
__device__ __forceinline__ uint32_t smem_u32(const void* p) {
    uint32_t a;
    asm("{ .reg .u64 t; cvta.to.shared.u64 t, %1; cvt.u32.u64 %0, t; }"
        : "=r"(a) : "l"(p));
    return a;
}
__device__ __forceinline__ uint32_t pack2bf(float a, float b) {
    __nv_bfloat162 t;
    t.x = __float2bfloat16_rn(a);
    t.y = __float2bfloat16_rn(b);
    return *(uint32_t*)&t;
}
__device__ __forceinline__ uint32_t pack2h(float a, float b) {
    __half2 t;
    t.x = __float2half_rn(a);
    t.y = __float2half_rn(b);
    return *(uint32_t*)&t;
}
__device__ __forceinline__ float fast_exp2(float x) {
    float r;
    asm("ex2.approx.ftz.f32 %0, %1;" : "=f"(r) : "f"(x));
    return r;
}

// ---------------------------------------------------------------------------
// Split-bf16 tensor-core GEMM.
// mode 0: QKV projection, epilogue writes Q->g_Qf (scaled fp16, per-head),
//         K->g_Kf (fp16, per-head), V->g_Vc (fp32 compact).
// mode 1: out projection (A=g_AO*, B=g_Wot*, bias=b0p, C=C_ext fp32).
// ---------------------------------------------------------------------------
#define GPIT 80
#define GAH 0
#define GAL 10240
#define GBH 20480
#define GBL 30720
#define GSTAGE 40960
#define GEMM_SMEM (2 * GSTAGE)

__global__ __launch_bounds__(256, 2) void gemm_mma_kernel(
    int mode, const float* __restrict__ b0p, const float* __restrict__ b1p,
    const float* __restrict__ b2p, float* __restrict__ C_ext)
{
    extern __shared__ char smem[];
    const __nv_bfloat16 *Ah, *Al, *Bth, *Btl;
    if (mode == 0) {
        Ah = g_Xh;  Al = g_Xl;  Bth = g_Wth;  Btl = g_Wtl;
    } else {
        Ah = g_AOh; Al = g_AOl; Bth = g_Woth; Btl = g_Wotl;
    }

    const int tid = threadIdx.x;
    const int w = tid >> 5, l = tid & 31, g = l >> 2, t = l & 3;
    const int n0 = blockIdx.x * 128;
    const int mb = blockIdx.y * 128;
    const uint32_t sbase = smem_u32(smem);

    auto load = [&](int kc, int st) {
        uint32_t b = sbase + st * GSTAGE;
        #pragma unroll
        for (int p = 0; p < 2; p++) {
            int i = tid + p * 256;
            int r = i >> 2, c = i & 3;
            uint32_t so = r * GPIT + c * 16;
            size_t ga = ((size_t)(mb + r) * 512 + kc * 32) * 2 + c * 16;
            cp16(b + GAH + so, (const char*)Ah + ga);
            cp16(b + GAL + so, (const char*)Al + ga);
            size_t gb = ((size_t)(n0 + r) * 512 + kc * 32) * 2 + c * 16;
            cp16(b + GBH + so, (const char*)Bth + gb);
            cp16(b + GBL + so, (const char*)Btl + gb);
        }
        asm volatile("cp.async.commit_group;" ::: "memory");
    };

    float acc[16][4];
    #pragma unroll
    for (int j = 0; j < 16; j++)
        #pragma unroll
        for (int i = 0; i < 4; i++) acc[j][i] = 0.0f;

    load(0, 0);
    for (int kc = 0; kc < 16; kc++) {
        if (kc + 1 < 16) {
            load(kc + 1, (kc + 1) & 1);
            asm volatile("cp.async.wait_group 1;" ::: "memory");
        } else {
            asm volatile("cp.async.wait_group 0;" ::: "memory");
        }
        __syncthreads();
        const char* S = smem + (kc & 1) * GSTAGE;

        #pragma unroll
        for (int kk = 0; kk < 2; kk++) {
            uint32_t ao = (uint32_t)(w * 16 + g) * GPIT + (uint32_t)(16 * kk + 2 * t) * 2;
            uint32_t ah[4], al[4];
            ah[0] = *(const uint32_t*)(S + GAH + ao);
            ah[1] = *(const uint32_t*)(S + GAH + ao + 8 * GPIT);
            ah[2] = *(const uint32_t*)(S + GAH + ao + 16);
            ah[3] = *(const uint32_t*)(S + GAH + ao + 8 * GPIT + 16);
            al[0] = *(const uint32_t*)(S + GAL + ao);
            al[1] = *(const uint32_t*)(S + GAL + ao + 8 * GPIT);
            al[2] = *(const uint32_t*)(S + GAL + ao + 16);
            al[3] = *(const uint32_t*)(S + GAL + ao + 8 * GPIT + 16);
            #pragma unroll
            for (int j = 0; j < 16; j++) {
                uint32_t bo = (uint32_t)(8 * j + g) * GPIT + (uint32_t)(16 * kk + 2 * t) * 2;
                uint32_t bh0 = *(const uint32_t*)(S + GBH + bo);
                uint32_t bh1 = *(const uint32_t*)(S + GBH + bo + 16);
                uint32_t bl0 = *(const uint32_t*)(S + GBL + bo);
                uint32_t bl1 = *(const uint32_t*)(S + GBL + bo + 16);
                mma_bf16(acc[j], ah, bh0, bh1);
                mma_bf16(acc[j], al, bh0, bh1);
                mma_bf16(acc[j], ah, bl0, bl1);
            }
        }
        __syncthreads();
    }

    const int r0 = mb + w * 16 + g, r1 = r0 + 8;
    if (mode == 1) {
        #pragma unroll
        for (int j = 0; j < 16; j++) {
            int col = n0 + 8 * j + 2 * t;
            float bv0 = b0p[col], bv1 = b0p[col + 1];
            *(float2*)&C_ext[(size_t)r0 * 512 + col] =
                make_float2(acc[j][0] + bv0, acc[j][1] + bv1);
            *(float2*)&C_ext[(size_t)r1 * 512 + col] =
                make_float2(acc[j][2] + bv0, acc[j][3] + bv1);
        }
    } else {
        const float QS = 0.125f * LOG2E;
        #pragma unroll
        for (int j = 0; j < 16; j++) {
            int col = n0 + 8 * j + 2 * t;
            const float* bp = (col < 512) ? b0p : (col < 1024 ? b1p : b2p);
            int cc = col & 511;
            float bv0 = bp[cc], bv1 = bp[cc + 1];
            float v00 = acc[j][0] + bv0, v01 = acc[j][1] + bv1;
            float v10 = acc[j][2] + bv0, v11 = acc[j][3] + bv1;
            if (col < 512) {
                int h = cc >> 6, d = cc & 63;
                *(uint32_t*)&g_Qf[((size_t)h * NTOK + r0) * HDIM + d] =
                    pack2h(v00 * QS, v01 * QS);
                *(uint32_t*)&g_Qf[((size_t)h * NTOK + r1) * HDIM + d] =
                    pack2h(v10 * QS, v11 * QS);
            } else if (col < 1024) {
                int h = cc >> 6, d = cc & 63;
                *(uint32_t*)&g_Kf[((size_t)h * NTOK + r0) * HDIM + d] = pack2h(v00, v01);
                *(uint32_t*)&g_Kf[((size_t)h * NTOK + r1) * HDIM + d] = pack2h(v10, v11);
            } else {
                *(float2*)&g_Vc[(size_t)r0 * 512 + cc] = make_float2(v00, v01);
                *(float2*)&g_Vc[(size_t)r1 * 512 + cc] = make_float2(v10, v11);
            }
        }
    }
}

// ---------------------------------------------------------------------------
// Fused input prep:
//   blocks [0,4096): z bins  |  [4096,5120): W transpose+split  |  [5120,9216): x split
// ---------------------------------------------------------------------------
__device__ __forceinline__ uint8_t bin_of(float z) {
    int b = (int)floorf(z / 5.0f * 16.0f);
    return (uint8_t)max(0, min(NBINS - 1, b));
}

__global__ __launch_bounds__(256) void prep_in_kernel(
    const float* __restrict__ x, const float* __restrict__ zmat,
    const float* __restrict__ Wq, const float* __restrict__ Wk,
    const float* __restrict__ Wv, const float* __restrict__ Wo)
{
    int bx = blockIdx.x;
    int tid = threadIdx.x;
    if (bx < 4096) {
        size_t i = (size_t)bx * 256 + tid;
        float4 z = *(const float4*)(zmat + i * 4);
        uchar4 b;
        b.x = bin_of(z.x); b.y = bin_of(z.y); b.z = bin_of(z.z); b.w = bin_of(z.w);
        *(uchar4*)(g_bins + i * 4) = b;
    } else if (bx < 5120) {
        __shared__ float ts[32][33];
        int bb = bx - 4096;
        int zb = bb >> 8, rem = bb & 255;
        int k0 = (rem & 15) * 32;
        int n0 = (rem >> 4) * 32;
        const float* src;
        __nv_bfloat16 *dh, *dl;
        int nbase;
        if (zb == 0)      { src = Wq; dh = g_Wth;  dl = g_Wtl;  nbase = 0; }
        else if (zb == 1) { src = Wk; dh = g_Wth;  dl = g_Wtl;  nbase = 512; }
        else if (zb == 2) { src = Wv; dh = g_Wth;  dl = g_Wtl;  nbase = 1024; }
        else              { src = Wo; dh = g_Woth; dl = g_Wotl; nbase = 0; }
        int tx = tid & 31, ty = tid >> 5;
        #pragma unroll
        for (int i = 0; i < 4; i++) {
            int r = ty + i * 8;
            ts[r][tx] = src[(size_t)(k0 + r) * 512 + n0 + tx];
        }
        __syncthreads();
        #pragma unroll
        for (int i = 0; i < 4; i++) {
            int nn = ty + i * 8;
            float v = ts[tx][nn];
            __nv_bfloat16 h = __float2bfloat16_rn(v);
            size_t dst = (size_t)(nbase + n0 + nn) * 512 + k0 + tx;
            dh[dst] = h;
            dl[dst] = __float2bfloat16_rn(v - __bfloat162float(h));
        }
    } else {
        int i = (bx - 5120) * 256 + tid;
        float v = x[i];
        __nv_bfloat16 h = __float2bfloat16_rn(v);
        g_Xh[i] = h;
        g_Xl[i] = __float2bfloat16_rn(v - __bfloat162float(h));
    }
}

// ---------------------------------------------------------------------------
// V transpose: g_Vc [tok][512] fp32 -> g_Vtf [h][d][2048] fp16
// ---------------------------------------------------------------------------
__global__ __launch_bounds__(256) void prep_vt_kernel()
{
    __shared__ float ts[32][33];
    int bx = blockIdx.x;
    int tok0 = (bx & 63) * 32;
    int c0   = (bx >> 6) * 32;
    int tid = threadIdx.x;
    int tx = tid & 31, ty = tid >> 5;
    #pragma unroll
    for (int i = 0; i < 4; i++) {
        int r = ty + i * 8;
        ts[r][tx] = g_Vc[(size_t)(tok0 + r) * 512 + c0 + tx];
    }
    __syncthreads();
    #pragma unroll
    for (int i = 0; i < 4; i++) {
        int dd = ty + i * 8;
        int col = c0 + dd, h = col >> 6, hd = col & 63;
        g_Vtf[((size_t)h * HDIM + hd) * NTOK + tok0 + tx] = __float2half_rn(ts[tx][dd]);
    }
}

// ---------------------------------------------------------------------------
// fp16 mma.sync flash attention; l accumulated via all-ones B-fragment MMAs.
// ---------------------------------------------------------------------------
#define KP 144
#define VP 272
#define BP 144
#define KF_O 0
#define VT_O 18432
#define BN_O 35840
#define STAGE 54272
#define ATTN_SMEM (2 * STAGE)

__global__ __launch_bounds__(256, 1) void attn_mma_kernel(const float* __restrict__ ztab)
{
    extern __shared__ char smem[];
    __shared__ float zt[NBINS];

    const int tid = threadIdx.x;
    const int w   = tid >> 5;
    const int l   = tid & 31;
    const int g   = l >> 2;
    const int t   = l & 3;
    const int h   = blockIdx.y;
    const int q0  = blockIdx.x * 128;
    const int m0  = w * 16;
    const uint32_t ONES2 = 0x3C003C00u;   // fp16 (1.0, 1.0)

    if (tid < NBINS) zt[tid] = ztab[tid * NH + h] * LOG2E;

    const uint32_t sbase = smem_u32(smem);

    auto load_tile = [&](int kt, int stage) {
        uint32_t base = sbase + stage * STAGE;
        #pragma unroll
        for (int p = 0; p < 4; p++) {
            int i = tid + p * 256;
            int r = i >> 3, c = i & 7;
            cp16(base + KF_O + r * KP + c * 16,
                 (const char*)g_Kf + (((size_t)h * NTOK + kt * 128 + r) * HDIM) * 2 + c * 16);
        }
        #pragma unroll
        for (int p = 0; p < 4; p++) {
            int i = tid + p * 256;
            int d = i >> 4, c = i & 15;
            cp16(base + VT_O + d * VP + c * 16,
                 (const char*)g_Vtf + (((size_t)h * HDIM + d) * NTOK + kt * 128) * 2 + c * 16);
        }
        #pragma unroll
        for (int p = 0; p < 4; p++) {
            int i = tid + p * 256;
            int r = i >> 3, c = i & 7;
            cp16(base + BN_O + r * BP + c * 16,
                 g_bins + (size_t)(q0 + r) * NTOK + kt * 128 + c * 16);
        }
        asm volatile("cp.async.commit_group;" ::: "memory");
    };

    load_tile(0, 0);

    uint32_t qf[4][4];
    {
        const uint16_t* qb = (const uint16_t*)g_Qf + ((size_t)h * NTOK + q0 + m0) * HDIM;
        #pragma unroll
        for (int kk = 0; kk < 4; kk++) {
            int c0 = 16 * kk + 2 * t;
            qf[kk][0] = *(const uint32_t*)(qb + (size_t)g * HDIM + c0);
            qf[kk][1] = *(const uint32_t*)(qb + (size_t)(g + 8) * HDIM + c0);
            qf[kk][2] = *(const uint32_t*)(qb + (size_t)g * HDIM + c0 + 8);
            qf[kk][3] = *(const uint32_t*)(qb + (size_t)(g + 8) * HDIM + c0 + 8);
        }
    }

    float oc[8][4];
    #pragma unroll
    for (int j = 0; j < 8; j++)
        #pragma unroll
        for (int i = 0; i < 4; i++) oc[j][i] = 0.0f;
    float lc[4] = {0.0f, 0.0f, 0.0f, 0.0f};

    for (int kt = 0; kt < NTOK / 128; kt++) {
        if (kt + 1 < NTOK / 128) {
            load_tile(kt + 1, (kt + 1) & 1);
            asm volatile("cp.async.wait_group 1;" ::: "memory");
        } else {
            asm volatile("cp.async.wait_group 0;" ::: "memory");
        }
        __syncthreads();

        const char* S = smem + (kt & 1) * STAGE;

        float sc[16][4];
        #pragma unroll
        for (int j = 0; j < 16; j++)
            #pragma unroll
            for (int i = 0; i < 4; i++) sc[j][i] = 0.0f;

        #pragma unroll
        for (int kk = 0; kk < 4; kk++) {
            #pragma unroll
            for (int j = 0; j < 16; j++) {
                uint32_t off = (uint32_t)(8 * j + g) * KP + (uint32_t)(16 * kk + 2 * t) * 2;
                uint32_t k0 = *(const uint32_t*)(S + KF_O + off);
                uint32_t k1 = *(const uint32_t*)(S + KF_O + off + 16);
                mma_fp16(sc[j], qf[kk], k0, k1);
            }
        }

        uint32_t ph[8][4];
        const char* BN = S + BN_O;
        #pragma unroll
        for (int j = 0; j < 16; j++) {
            int col = 8 * j + 2 * t;
            uint16_t bA = *(const uint16_t*)(BN + (uint32_t)(m0 + g) * BP + col);
            uint16_t bB = *(const uint16_t*)(BN + (uint32_t)(m0 + g + 8) * BP + col);
            float p0 = fast_exp2(sc[j][0] + zt[bA & 0xFF]);
            float p1 = fast_exp2(sc[j][1] + zt[bA >> 8]);
            float p2 = fast_exp2(sc[j][2] + zt[bB & 0xFF]);
            float p3 = fast_exp2(sc[j][3] + zt[bB >> 8]);
            int kp = j >> 1, hf = (j & 1) * 2;
            ph[kp][hf + 0] = pack2h(p0, p1);
            ph[kp][hf + 1] = pack2h(p2, p3);
        }

        #pragma unroll
        for (int kp = 0; kp < 8; kp++) {
            mma_fp16(lc, ph[kp], ONES2, ONES2);   // l += row-sums of P
            #pragma unroll
            for (int jj = 0; jj < 8; jj++) {
                uint32_t off = (uint32_t)(8 * jj + g) * VP + (uint32_t)(16 * kp + 2 * t) * 2;
                uint32_t v0 = *(const uint32_t*)(S + VT_O + off);
                uint32_t v1 = *(const uint32_t*)(S + VT_O + off + 16);
                mma_fp16(oc[jj], ph[kp], v0, v1);
            }
        }
        __syncthreads();
    }

    float inv0 = 1.0f / lc[0], inv1 = 1.0f / lc[2];

    int r0 = q0 + m0 + g, r1 = r0 + 8;
    #pragma unroll
    for (int jj = 0; jj < 8; jj++) {
        int col = h * HDIM + 8 * jj + 2 * t;
        float v00 = oc[jj][0] * inv0, v01 = oc[jj][1] * inv0;
        float v10 = oc[jj][2] * inv1, v11 = oc[jj][3] * inv1;
        __nv_bfloat16 h00 = __float2bfloat16_rn(v00);
        __nv_bfloat16 h01 = __float2bfloat16_rn(v01);
        __nv_bfloat16 h10 = __float2bfloat16_rn(v10);
        __nv_bfloat16 h11 = __float2bfloat16_rn(v11);
        __nv_bfloat162 u0; u0.x = h00; u0.y = h01;
        __nv_bfloat162 u1; u1.x = h10; u1.y = h11;
        *(uint32_t*)&g_AOh[(size_t)r0 * DMOD + col] = *(uint32_t*)&u0;
        *(uint32_t*)&g_AOh[(size_t)r1 * DMOD + col] = *(uint32_t*)&u1;
        *(uint32_t*)&g_AOl[(size_t)r0 * DMOD + col] =
            pack2bf(v00 - __bfloat162float(h00), v01 - __bfloat162float(h01));
        *(uint32_t*)&g_AOl[(size_t)r1 * DMOD + col] =
            pack2bf(v10 - __bfloat162float(h10), v11 - __bfloat162float(h11));
    }
}

// ---------------------------------------------------------------------------

extern "C" void kernel_launch(void* const* d_in, const int* in_sizes, int n_in,
                              void* d_out, int out_size)
{
    const float* x  = (const float*)d_in[0];
    const float* z  = (const float*)d_in[1];
    const float* Wq = (const float*)d_in[2];
    const float* bq = (const float*)d_in[3];
    const float* Wk = (const float*)d_in[4];
    const float* bk = (const float*)d_in[5];
    const float* Wv = (const float*)d_in[6];
    const float* bv = (const float*)d_in[7];
    const float* Wo = (const float*)d_in[8];
    const float* bo = (const float*)d_in[9];
    const float* zt = (const float*)d_in[10];
    float* out = (float*)d_out;

    cudaFuncSetAttribute(attn_mma_kernel,
                         cudaFuncAttributeMaxDynamicSharedMemorySize, ATTN_SMEM);
    cudaFuncSetAttribute(gemm_mma_kernel,
                         cudaFuncAttributeMaxDynamicSharedMemorySize, GEMM_SMEM);

    // fused prep: bins + W transpose/split + x split
    prep_in_kernel<<<9216, 256>>>(x, z, Wq, Wk, Wv, Wo);

    // fused QKV projection; epilogue emits Qf/Kf (fp16) and Vc (fp32)
    gemm_mma_kernel<<<dim3(12, 16), 256, GEMM_SMEM>>>(0, bq, bk, bv, nullptr);

    // V transpose -> fp16 [h][d][2048]
    prep_vt_kernel<<<1024, 256>>>();

    attn_mma_kernel<<<dim3(NTOK / 128, NH), 256, ATTN_SMEM>>>(zt);

    // output projection
    gemm_mma_kernel<<<dim3(4, 16), 256, GEMM_SMEM>>>(1, bo, nullptr, nullptr, out);
}